// round 10
// baseline (speedup 1.0000x reference)
#include <cuda_runtime.h>
#include <cstdint>

// Problem constants
#define NN 40000
#define EE 640000
#define DD 128
#define EDD 16
#define LL 3
#define BN_INV 0.99999500003749978f  // 1/sqrt(1+1e-5)

// Scratch (no cudaMalloc allowed)
__device__ float  g_h[(size_t)NN * DD];
__device__ float  g_h2[(size_t)NN * DD];
__device__ float  g_agg[(size_t)NN * DD];
__device__ float  g_t[(size_t)NN * 2 * DD];
__device__ float2 g_pre[NN];
__device__ int    g_deg[NN];
__device__ int    g_off[NN + 1];
__device__ int    g_cur[NN];
__device__ int2   g_ecsr[EE];   // (src node, original edge id) per CSR slot

// ---- f32x2 helpers --------------------------------------------------------
__device__ __forceinline__ unsigned long long pack2(float lo, float hi) {
    unsigned long long r;
    asm("mov.b64 %0, {%1, %2};" : "=l"(r) : "f"(lo), "f"(hi));
    return r;
}
__device__ __forceinline__ void ffma2(unsigned long long& d,
                                      unsigned long long a,
                                      unsigned long long b) {
    asm("fma.rn.f32x2 %0, %1, %2, %0;" : "+l"(d) : "l"(a), "l"(b));
}
__device__ __forceinline__ void unpack2(unsigned long long v, float& lo, float& hi) {
    asm("mov.b64 {%0, %1}, %2;" : "=f"(lo), "=f"(hi) : "l"(v));
}
__device__ __forceinline__ float fold2(unsigned long long v) {
    float lo, hi; unpack2(v, lo, hi); return lo + hi;
}

// ---------------------------------------------------------------------------
// CSR build: (deg zeroed by cudaMemsetAsync) count -> scan -> fill
// ---------------------------------------------------------------------------
__global__ void count_kernel(const int* __restrict__ dst, int* __restrict__ deg) {
    int e = blockIdx.x * blockDim.x + threadIdx.x;
    if (e < EE) atomicAdd(&deg[dst[e]], 1);
}

__global__ __launch_bounds__(1024)
void scan_kernel(const int* __restrict__ deg, int* __restrict__ off,
                 int* __restrict__ cur) {
    __shared__ int part[1024];
    const int tid = threadIdx.x;
    const int per = (NN + 1023) / 1024;   // 40
    const int base = tid * per;
    int s = 0;
#pragma unroll 4
    for (int i = 0; i < per; i++) {
        const int n = base + i;
        if (n < NN) s += deg[n];
    }
    part[tid] = s;
    __syncthreads();
    for (int ofs = 1; ofs < 1024; ofs <<= 1) {
        int v = (tid >= ofs) ? part[tid - ofs] : 0;
        __syncthreads();
        part[tid] += v;
        __syncthreads();
    }
    int run = (tid > 0) ? part[tid - 1] : 0;   // exclusive prefix
    for (int i = 0; i < per; i++) {
        const int n = base + i;
        if (n < NN) {
            off[n] = run;
            cur[n] = run;
            run += deg[n];
        }
    }
    if (tid == 1023) off[NN] = EE;
}

__global__ void fill_kernel(const int* __restrict__ src,
                            const int* __restrict__ dst,
                            int* __restrict__ cur,
                            int2* __restrict__ ecsr) {
    int e = blockIdx.x * blockDim.x + threadIdx.x;
    if (e >= EE) return;
    const int d = dst[e];
    const int p = atomicAdd(&cur[d], 1);
    ecsr[p] = make_int2(src[e], e);
}

// ---------------------------------------------------------------------------
// prep: pre[n] = (h[n]·attn_W[0:128], h[n]·attn_W[128:256]). Warp per node.
// ---------------------------------------------------------------------------
__global__ __launch_bounds__(128)
void prep_kernel(const float* __restrict__ h,
                 const float* __restrict__ attn_W,   // [256]
                 float2* __restrict__ pre) {
    const int warp = (blockIdx.x * blockDim.x + threadIdx.x) >> 5;
    const int lane = threadIdx.x & 31;
    if (warp >= NN) return;
    const int d0 = lane * 4;
    const float4 hv = *(const float4*)(h + (size_t)warp * DD + d0);
    const float4 wi = *(const float4*)(attn_W + d0);
    const float4 wj = *(const float4*)(attn_W + DD + d0);
    float pi = hv.x * wi.x + hv.y * wi.y + hv.z * wi.z + hv.w * wi.w;
    float pj = hv.x * wj.x + hv.y * wj.y + hv.z * wj.z + hv.w * wj.w;
#pragma unroll
    for (int off = 16; off > 0; off >>= 1) {
        pi += __shfl_xor_sync(0xffffffffu, pi, off);
        pj += __shfl_xor_sync(0xffffffffu, pj, off);
    }
    if (lane == 0) pre[warp] = make_float2(pi, pj);
}

// ---------------------------------------------------------------------------
// CSR edge kernel v4: TWO warps per destination node (64 dims / warp,
// 2 dims / lane). Halved per-warp chains + higher occupancy.
// ---------------------------------------------------------------------------
__global__ __launch_bounds__(128, 4)
void edge_csr_kernel(const float* __restrict__ h,
                     const float* __restrict__ edge_attr,
                     const int* __restrict__ off,
                     const int2* __restrict__ ecsr,
                     const float* __restrict__ edge_W,   // [16,128]
                     const float* __restrict__ edge_b,   // [128]
                     const float2* __restrict__ pre,     // [N]
                     const float* __restrict__ attn_b,   // [1]
                     const float* __restrict__ eps_l,
                     float* __restrict__ agg) {
    const int lane = threadIdx.x & 31;
    const int gw = (blockIdx.x * blockDim.x + threadIdx.x) >> 5;
    const int node = gw >> 1;
    const int half = gw & 1;
    if (node >= NN) return;
    const int d0 = half * 64 + lane * 2;   // this lane's two dims

    // Weights for dims d0/d0+1, packed (k even, k odd): 16 x 64-bit regs
    unsigned long long wE2[16];
#pragma unroll
    for (int k2 = 0; k2 < 8; k2++) {
        const float2 wa = *(const float2*)(edge_W + (2 * k2) * DD + d0);
        const float2 wb = *(const float2*)(edge_W + (2 * k2 + 1) * DD + d0);
        wE2[k2]     = pack2(wa.x, wb.x);   // dim d0
        wE2[8 + k2] = pack2(wa.y, wb.y);   // dim d0+1
    }
    unsigned long long ebp0, ebp1;
    {
        const float2 eb = *(const float2*)(edge_b + d0);
        ebp0 = pack2(eb.x, 0.0f);
        ebp1 = pack2(eb.y, 0.0f);
    }
    const int beg = off[node], end = off[node + 1];
    const int deg = end - beg;
    const int m = (deg < 32) ? deg : 32;
    const float pd = __ldg(&pre[node].x) + attn_b[0];

    float2 acc;
    {
        const float s = 1.0f + eps_l[0];
        const float2 hv = *(const float2*)(h + (size_t)node * DD + d0);
        acc.x = hv.x * s; acc.y = hv.y * s;
    }

    // One lane-vector load covers up to 32 edges of this node.
    int2 se = make_int2(0, 0);
    if (lane < m) se = __ldg(&ecsr[beg + lane]);

    const int ngrp = (m + 1) >> 1;
#pragma unroll 1
    for (int g = 0; g < ngrp; g++) {
        const int base = g * 2;
        int sI[2], iI[2];
        float vm[2];
#pragma unroll
        for (int u = 0; u < 2; u++) {
            const int e = base + u;
            sI[u] = __shfl_sync(0xffffffffu, se.x, e & 31);
            iI[u] = __shfl_sync(0xffffffffu, se.y, e & 31);
            vm[u] = (e < m) ? 1.0f : 0.0f;
        }
        // Batched loads: 2 gathers (float2) + 2 attr rows (broadcast) + 2 pre
        float2 xj[2]; float pj[2];
        ulonglong2 q[2][4];
#pragma unroll
        for (int u = 0; u < 2; u++) {
            xj[u] = *(const float2*)(h + (size_t)sI[u] * DD + d0);
            pj[u] = __ldg(&pre[sI[u]].y);
            const ulonglong2* ea = (const ulonglong2*)(edge_attr + (size_t)iI[u] * EDD);
            q[u][0] = __ldg(ea + 0); q[u][1] = __ldg(ea + 1);
            q[u][2] = __ldg(ea + 2); q[u][3] = __ldg(ea + 3);
        }
#pragma unroll
        for (int u = 0; u < 2; u++) {
            const float a = 1.0f / (1.0f + __expf(-(pd + pj[u])));
            const unsigned long long ep[8] = {q[u][0].x, q[u][0].y, q[u][1].x, q[u][1].y,
                                              q[u][2].x, q[u][2].y, q[u][3].x, q[u][3].y};
            unsigned long long av0 = ebp0, av1 = ebp1;
#pragma unroll
            for (int k2 = 0; k2 < 8; k2++) {
                ffma2(av0, ep[k2], wE2[k2]);
                ffma2(av1, ep[k2], wE2[8 + k2]);
            }
            acc.x = fmaf(fmaxf(fmaf(xj[u].x, a, fold2(av0)), 0.0f), vm[u], acc.x);
            acc.y = fmaf(fmaxf(fmaf(xj[u].y, a, fold2(av1)), 0.0f), vm[u], acc.y);
        }
    }

    // Rare overflow: degree > 32
#pragma unroll 1
    for (int j = beg + 32; j < end; j++) {
        const int2 e2 = __ldg(&ecsr[j]);
        const float2 xj = *(const float2*)(h + (size_t)e2.x * DD + d0);
        const float pj = __ldg(&pre[e2.x].y);
        const ulonglong2* ea = (const ulonglong2*)(edge_attr + (size_t)e2.y * EDD);
        const ulonglong2 q0 = __ldg(ea + 0), q1 = __ldg(ea + 1),
                         q2 = __ldg(ea + 2), q3 = __ldg(ea + 3);
        const float a = 1.0f / (1.0f + __expf(-(pd + pj)));
        const unsigned long long ep[8] = {q0.x, q0.y, q1.x, q1.y,
                                          q2.x, q2.y, q3.x, q3.y};
        unsigned long long av0 = ebp0, av1 = ebp1;
#pragma unroll
        for (int k2 = 0; k2 < 8; k2++) {
            ffma2(av0, ep[k2], wE2[k2]);
            ffma2(av1, ep[k2], wE2[8 + k2]);
        }
        acc.x += fmaxf(fmaf(xj.x, a, fold2(av0)), 0.0f);
        acc.y += fmaxf(fmaf(xj.y, a, fold2(av1)), 0.0f);
    }

    *(float2*)(agg + (size_t)node * DD + d0) = acc;
}

// ---------------------------------------------------------------------------
// SGEMM: 128 threads, 128x128 tile, 16x8 per-thread, scalar FFMA core,
// 4-stage cp.async(B) pipeline, ONE barrier per k-tile (race-free at S=4).
// a_cs / c_cs: evict-first (streaming) hints for transient A reads / C writes.
// ---------------------------------------------------------------------------
__global__ __launch_bounds__(128, 3)
void sgemm_kernel(const float* __restrict__ A, const float* __restrict__ B,
                  const float* __restrict__ bias,
                  const float* __restrict__ bn_g, const float* __restrict__ bn_b,
                  float* __restrict__ C,
                  int M, int K, int Nc, int do_relu, int do_bn,
                  int a_cs, int c_cs) {
    __shared__ float As[4][8][128];   // [stage][k][row]
    __shared__ float Bs[4][8][128];   // [stage][k][col]

    const int tid = threadIdx.x;
    const int tx = tid & 15;
    const int ty = tid >> 4;
    const int row0 = blockIdx.y * 128;
    const int col0 = blockIdx.x * 128;

    const int a_row = tid >> 1;
    const int a_col = (tid & 1) * 4;
    const int b_row = tid >> 4;
    const int b_col = (tid & 15) * 8;

    const int gr1 = row0 + a_row, gr2 = gr1 + 64;
    const bool v1 = gr1 < M, v2 = gr2 < M;
    const float* aptr1 = A + (size_t)gr1 * K + a_col;
    const float* aptr2 = A + (size_t)gr2 * K + a_col;
    const float* bptr  = B + (size_t)b_row * Nc + col0 + b_col;

    const int nt = K >> 3;
    const float4 f40 = make_float4(0.f, 0.f, 0.f, 0.f);
    float4 ar0, ar1;

#define LDG_A(k0) { \
    ar0 = v1 ? (a_cs ? __ldcs((const float4*)(aptr1 + (k0))) \
                     : *(const float4*)(aptr1 + (k0))) : f40; \
    ar1 = v2 ? (a_cs ? __ldcs((const float4*)(aptr2 + (k0))) \
                     : *(const float4*)(aptr2 + (k0))) : f40; }
#define STS_A(stg) { As[stg][a_col+0][a_row] = ar0.x; As[stg][a_col+1][a_row] = ar0.y; \
                     As[stg][a_col+2][a_row] = ar0.z; As[stg][a_col+3][a_row] = ar0.w; \
                     As[stg][a_col+0][a_row+64] = ar1.x; As[stg][a_col+1][a_row+64] = ar1.y; \
                     As[stg][a_col+2][a_row+64] = ar1.z; As[stg][a_col+3][a_row+64] = ar1.w; }
#define CP_B(stg, k0) { \
    uint32_t _d = (uint32_t)__cvta_generic_to_shared(&Bs[stg][b_row][b_col]); \
    const float* _s = bptr + (size_t)(k0) * Nc; \
    asm volatile("cp.async.cg.shared.global [%0], [%1], 16;\n\t" \
                 "cp.async.cg.shared.global [%2], [%3], 16;\n\t" \
                 "cp.async.commit_group;\n" \
                 :: "r"(_d), "l"(_s), "r"(_d + 16), "l"(_s + 4) : "memory"); }

    float acc[16][8];
#pragma unroll
    for (int i = 0; i < 16; i++)
#pragma unroll
        for (int j = 0; j < 8; j++) acc[i][j] = 0.0f;

    // Prologue: tiles 0 and 1
    LDG_A(0); CP_B(0, 0); STS_A(0);
    LDG_A(8); CP_B(1, 8);

#pragma unroll 1
    for (int t = 0; t < nt; t++) {
        const int st = t & 3;
        if (t + 1 < nt) STS_A((t + 1) & 3);
        if (t + 2 < nt) { const int k0 = (t + 2) * 8; LDG_A(k0); CP_B((t + 2) & 3, k0); }
        const int rem = nt - 1 - t;
        if (rem >= 2)      asm volatile("cp.async.wait_group 2;" ::: "memory");
        else if (rem == 1) asm volatile("cp.async.wait_group 1;" ::: "memory");
        else               asm volatile("cp.async.wait_group 0;" ::: "memory");
        __syncthreads();

#pragma unroll
        for (int k = 0; k < 8; k++) {
            float af[16], bf[8];
            *(float4*)&af[0]  = *(const float4*)&As[st][k][ty * 16];
            *(float4*)&af[4]  = *(const float4*)&As[st][k][ty * 16 + 4];
            *(float4*)&af[8]  = *(const float4*)&As[st][k][ty * 16 + 8];
            *(float4*)&af[12] = *(const float4*)&As[st][k][ty * 16 + 12];
            *(float4*)&bf[0]  = *(const float4*)&Bs[st][k][tx * 8];
            *(float4*)&bf[4]  = *(const float4*)&Bs[st][k][tx * 8 + 4];
#pragma unroll
            for (int i = 0; i < 16; i++)
#pragma unroll
                for (int j = 0; j < 8; j++)
                    acc[i][j] = fmaf(af[i], bf[j], acc[i][j]);
        }
    }

    // Epilogue
    float bi[8], g[8], bb[8];
#pragma unroll
    for (int j = 0; j < 8; j++) {
        const int c = col0 + tx * 8 + j;
        bi[j] = bias[c];
        if (do_bn) { g[j] = bn_g[c]; bb[j] = bn_b[c]; }
    }
#pragma unroll
    for (int i = 0; i < 16; i++) {
        const int r = row0 + ty * 16 + i;
        if (r >= M) continue;
        float v[8];
#pragma unroll
        for (int j = 0; j < 8; j++) {
            float t = acc[i][j] + bi[j];
            if (do_bn) t = fmaf(g[j] * BN_INV, t, bb[j]);
            if (do_relu) t = fmaxf(t, 0.0f);
            v[j] = t;
        }
        float* cp = C + (size_t)r * Nc + col0 + tx * 8;
        const float4 o0 = make_float4(v[0], v[1], v[2], v[3]);
        const float4 o1 = make_float4(v[4], v[5], v[6], v[7]);
        if (c_cs) { __stcs((float4*)cp, o0); __stcs((float4*)(cp + 4), o1); }
        else      { *(float4*)cp = o0;       *(float4*)(cp + 4) = o1; }
    }
#undef LDG_A
#undef STS_A
#undef CP_B
}

// ---------------------------------------------------------------------------
extern "C" void kernel_launch(void* const* d_in, const int* in_sizes, int n_in,
                              void* d_out, int out_size) {
    const float* x         = (const float*)d_in[0];
    const float* edge_attr = (const float*)d_in[1];
    const float* node_W    = (const float*)d_in[2];
    const float* node_b    = (const float*)d_in[3];
    const float* edge_W    = (const float*)d_in[4];
    const float* edge_b    = (const float*)d_in[5];
    const float* attn_W    = (const float*)d_in[6];
    const float* attn_b    = (const float*)d_in[7];
    const float* eps       = (const float*)d_in[8];
    const float* W1        = (const float*)d_in[9];
    const float* b1        = (const float*)d_in[10];
    const float* bn1_g     = (const float*)d_in[11];
    const float* bn1_b     = (const float*)d_in[12];
    const float* W2        = (const float*)d_in[13];
    const float* b2        = (const float*)d_in[14];
    const float* bn_g      = (const float*)d_in[15];
    const float* bn_b      = (const float*)d_in[16];
    const int*   edge_index= (const int*)d_in[17];

    float *hA, *hB, *agg, *tbuf; float2* pre;
    int *deg, *off, *cur; int2* ecsr;
    cudaGetSymbolAddress((void**)&hA,   g_h);
    cudaGetSymbolAddress((void**)&hB,   g_h2);
    cudaGetSymbolAddress((void**)&agg,  g_agg);
    cudaGetSymbolAddress((void**)&tbuf, g_t);
    cudaGetSymbolAddress((void**)&pre,  g_pre);
    cudaGetSymbolAddress((void**)&deg,  g_deg);
    cudaGetSymbolAddress((void**)&off,  g_off);
    cudaGetSymbolAddress((void**)&cur,  g_cur);
    cudaGetSymbolAddress((void**)&ecsr, g_ecsr);

    const int* src_arr = edge_index;
    const int* dst_arr = edge_index + EE;
    const int mblk = (NN + 127) / 128;     // 313

    // CSR build (deg zeroed via memset node — graph-capturable, not an alloc)
    cudaMemsetAsync(deg, 0, NN * sizeof(int));
    count_kernel<<<(EE + 255) / 256, 256>>>(dst_arr, deg);
    scan_kernel<<<1, 1024>>>(deg, off, cur);
    fill_kernel<<<(EE + 255) / 256, 256>>>(src_arr, dst_arr, cur, ecsr);

    // node encoder: h = x @ node_W + node_b   (x streamed, h kept resident)
    sgemm_kernel<<<dim3(1, mblk), 128>>>(x, node_W, node_b, nullptr, nullptr,
                                         hA, NN, DD, DD, 0, 0, 1, 0);

    const float* hcur = hA;
    float* hnext = hB;
    for (int l = 0; l < LL; l++) {
        prep_kernel<<<10000, 128>>>(hcur, attn_W + (size_t)l * 2 * DD, pre);
        edge_csr_kernel<<<20000, 128>>>(hcur, edge_attr, off, ecsr,
                                        edge_W + (size_t)l * EDD * DD,
                                        edge_b + (size_t)l * DD,
                                        pre, attn_b + l, eps + l, agg);
        // t = relu(bn1(agg @ W1 + b1))   [N,128]@[128,256]  (agg, t streamed)
        sgemm_kernel<<<dim3(2, mblk), 128>>>(agg, W1 + (size_t)l * DD * 2 * DD,
                                             b1 + (size_t)l * 2 * DD,
                                             bn1_g + (size_t)l * 2 * DD,
                                             bn1_b + (size_t)l * 2 * DD,
                                             tbuf, NN, DD, 2 * DD, 1, 1, 1, 1);
        // h' = [relu] bn(t @ W2 + b2)    [N,256]@[256,128]  (t streamed; h kept)
        float* outp = (l == LL - 1) ? (float*)d_out : hnext;
        sgemm_kernel<<<dim3(1, mblk), 128>>>(tbuf, W2 + (size_t)l * 2 * DD * DD,
                                             b2 + (size_t)l * DD,
                                             bn_g + (size_t)l * DD,
                                             bn_b + (size_t)l * DD,
                                             outp, NN, 2 * DD, DD,
                                             (l < LL - 1) ? 1 : 0, 1,
                                             1, (l == LL - 1) ? 1 : 0);
        if (l < LL - 1) {
            hcur = outp;
            hnext = (outp == hA) ? hB : hA;
        }
    }
}

// round 11
// speedup vs baseline: 1.5780x; 1.5780x over previous
#include <cuda_runtime.h>
#include <cstdint>

// Problem constants
#define NN 40000
#define EE 640000
#define DD 128
#define EDD 16
#define LL 3
#define BN_INV 0.99999500003749978f  // 1/sqrt(1+1e-5)

// Scratch (no cudaMalloc allowed)
__device__ float  g_h[(size_t)NN * DD];
__device__ float  g_h2[(size_t)NN * DD];
__device__ float  g_agg[(size_t)NN * DD];
__device__ float  g_t[(size_t)NN * 2 * DD];
__device__ float2 g_pre[NN];
__device__ int    g_deg[NN];
__device__ int    g_off[NN + 1];
__device__ int    g_cur[NN];
__device__ int    g_esrc[EE];                 // src node per CSR slot
__device__ float  g_ea[(size_t)EE * EDD];     // edge_attr reordered to CSR slots

// ---- f32x2 helpers --------------------------------------------------------
__device__ __forceinline__ unsigned long long pack2(float lo, float hi) {
    unsigned long long r;
    asm("mov.b64 %0, {%1, %2};" : "=l"(r) : "f"(lo), "f"(hi));
    return r;
}
__device__ __forceinline__ void ffma2(unsigned long long& d,
                                      unsigned long long a,
                                      unsigned long long b) {
    asm("fma.rn.f32x2 %0, %1, %2, %0;" : "+l"(d) : "l"(a), "l"(b));
}
__device__ __forceinline__ void unpack2(unsigned long long v, float& lo, float& hi) {
    asm("mov.b64 {%0, %1}, %2;" : "=f"(lo), "=f"(hi) : "l"(v));
}
__device__ __forceinline__ float fold2(unsigned long long v) {
    float lo, hi; unpack2(v, lo, hi); return lo + hi;
}

// ---------------------------------------------------------------------------
// CSR build: (deg zeroed by cudaMemsetAsync) count -> scan -> fill
// fill also reorders edge_attr rows into CSR slot order (ea_csr).
// ---------------------------------------------------------------------------
__global__ void count_kernel(const int* __restrict__ dst, int* __restrict__ deg) {
    int e = blockIdx.x * blockDim.x + threadIdx.x;
    if (e < EE) atomicAdd(&deg[dst[e]], 1);
}

__global__ __launch_bounds__(1024)
void scan_kernel(const int* __restrict__ deg, int* __restrict__ off,
                 int* __restrict__ cur) {
    __shared__ int part[1024];
    const int tid = threadIdx.x;
    const int per = (NN + 1023) / 1024;   // 40
    const int base = tid * per;
    int s = 0;
#pragma unroll 4
    for (int i = 0; i < per; i++) {
        const int n = base + i;
        if (n < NN) s += deg[n];
    }
    part[tid] = s;
    __syncthreads();
    for (int ofs = 1; ofs < 1024; ofs <<= 1) {
        int v = (tid >= ofs) ? part[tid - ofs] : 0;
        __syncthreads();
        part[tid] += v;
        __syncthreads();
    }
    int run = (tid > 0) ? part[tid - 1] : 0;   // exclusive prefix
    for (int i = 0; i < per; i++) {
        const int n = base + i;
        if (n < NN) {
            off[n] = run;
            cur[n] = run;
            run += deg[n];
        }
    }
    if (tid == 1023) off[NN] = EE;
}

__global__ void fill_kernel(const int* __restrict__ src,
                            const int* __restrict__ dst,
                            const float* __restrict__ edge_attr,
                            int* __restrict__ cur,
                            int* __restrict__ esrc,
                            float* __restrict__ ea_csr) {
    int e = blockIdx.x * blockDim.x + threadIdx.x;
    if (e >= EE) return;
    const int d = dst[e];
    const int p = atomicAdd(&cur[d], 1);
    esrc[p] = src[e];
    const float4* s4 = (const float4*)(edge_attr + (size_t)e * EDD);
    float4* d4 = (float4*)(ea_csr + (size_t)p * EDD);
    d4[0] = s4[0]; d4[1] = s4[1]; d4[2] = s4[2]; d4[3] = s4[3];
}

// ---------------------------------------------------------------------------
// prep: pre[n] = (h[n]·attn_W[0:128], h[n]·attn_W[128:256]). Warp per node.
// ---------------------------------------------------------------------------
__global__ __launch_bounds__(128)
void prep_kernel(const float* __restrict__ h,
                 const float* __restrict__ attn_W,   // [256]
                 float2* __restrict__ pre) {
    const int warp = (blockIdx.x * blockDim.x + threadIdx.x) >> 5;
    const int lane = threadIdx.x & 31;
    if (warp >= NN) return;
    const int d0 = lane * 4;
    const float4 hv = *(const float4*)(h + (size_t)warp * DD + d0);
    const float4 wi = *(const float4*)(attn_W + d0);
    const float4 wj = *(const float4*)(attn_W + DD + d0);
    float pi = hv.x * wi.x + hv.y * wi.y + hv.z * wi.z + hv.w * wi.w;
    float pj = hv.x * wj.x + hv.y * wj.y + hv.z * wj.z + hv.w * wj.w;
#pragma unroll
    for (int off = 16; off > 0; off >>= 1) {
        pi += __shfl_xor_sync(0xffffffffu, pi, off);
        pj += __shfl_xor_sync(0xffffffffu, pj, off);
    }
    if (lane == 0) pre[warp] = make_float2(pi, pj);
}

// ---------------------------------------------------------------------------
// CSR edge kernel v5: warp per destination node.
//  - one lane-vector LDG for <=32 src ids, one warp-wide gather for their pre.y
//  - 8-edge h[src] gather batches (MLP=8)
//  - ea rows read SEQUENTIALLY from CSR-reordered ea_csr
// ---------------------------------------------------------------------------
__global__ __launch_bounds__(128, 3)
void edge_csr_kernel(const float* __restrict__ h,
                     const float* __restrict__ ea_csr,
                     const int* __restrict__ off,
                     const int* __restrict__ esrc,
                     const float* __restrict__ edge_W,   // [16,128]
                     const float* __restrict__ edge_b,   // [128]
                     const float2* __restrict__ pre,     // [N]
                     const float* __restrict__ attn_b,   // [1]
                     const float* __restrict__ eps_l,
                     float* __restrict__ agg) {
    const int lane = threadIdx.x & 31;
    const int node = (blockIdx.x * blockDim.x + threadIdx.x) >> 5;
    if (node >= NN) return;
    const int d0 = lane * 4;

    // edge weights packed (k even, k odd) per output dim
    unsigned long long wE2[32];
#pragma unroll
    for (int k2 = 0; k2 < 8; k2++) {
        const float4 wa = *(const float4*)(edge_W + (2 * k2) * DD + d0);
        const float4 wb = *(const float4*)(edge_W + (2 * k2 + 1) * DD + d0);
        wE2[k2 * 4 + 0] = pack2(wa.x, wb.x);
        wE2[k2 * 4 + 1] = pack2(wa.y, wb.y);
        wE2[k2 * 4 + 2] = pack2(wa.z, wb.z);
        wE2[k2 * 4 + 3] = pack2(wa.w, wb.w);
    }
    unsigned long long ebp[4];
    {
        const float4 eb = *(const float4*)(edge_b + d0);
        ebp[0] = pack2(eb.x, 0.0f); ebp[1] = pack2(eb.y, 0.0f);
        ebp[2] = pack2(eb.z, 0.0f); ebp[3] = pack2(eb.w, 0.0f);
    }
    const int beg = off[node], end = off[node + 1];
    const int deg = end - beg;
    const int m = (deg < 32) ? deg : 32;
    const float pd = __ldg(&pre[node].x) + attn_b[0];

    float4 acc;
    {
        const float s = 1.0f + eps_l[0];
        const float4 hv = *(const float4*)(h + (size_t)node * DD + d0);
        acc.x = hv.x * s; acc.y = hv.y * s; acc.z = hv.z * s; acc.w = hv.w * s;
    }

    // Lane-vector fetch: src ids + their attention dots, one load each.
    int sl = 0;
    if (lane < m) sl = __ldg(&esrc[beg + lane]);
    float ppl = 0.0f;
    if (lane < m) ppl = __ldg(&pre[sl].y);

    const int ngrp = (m + 7) >> 3;
#pragma unroll 1
    for (int g = 0; g < ngrp; g++) {
        const int base = g * 8;
        int sI[8]; float pj[8], vm[8];
#pragma unroll
        for (int u = 0; u < 8; u++) {
            const int e = base + u;
            sI[u] = __shfl_sync(0xffffffffu, sl, e & 31);
            pj[u] = __shfl_sync(0xffffffffu, ppl, e & 31);
            vm[u] = (e < m) ? 1.0f : 0.0f;
        }
        // 8 independent gathers in flight
        float4 xj[8];
#pragma unroll
        for (int u = 0; u < 8; u++)
            xj[u] = *(const float4*)(h + (size_t)sI[u] * DD + d0);

#pragma unroll
        for (int u = 0; u < 8; u++) {
            const int e = base + u;
            const float a = 1.0f / (1.0f + __expf(-(pd + pj[u])));
            const int slot = beg + ((e < m) ? e : 0);   // safe sequential slot
            const ulonglong2* ea = (const ulonglong2*)(ea_csr + (size_t)slot * EDD);
            const ulonglong2 q0 = __ldg(ea + 0), q1 = __ldg(ea + 1),
                             q2 = __ldg(ea + 2), q3 = __ldg(ea + 3);
            const unsigned long long ep[8] = {q0.x, q0.y, q1.x, q1.y,
                                              q2.x, q2.y, q3.x, q3.y};
            unsigned long long av0 = ebp[0], av1 = ebp[1],
                               av2 = ebp[2], av3 = ebp[3];
#pragma unroll
            for (int k2 = 0; k2 < 8; k2++) {
                ffma2(av0, ep[k2], wE2[k2 * 4 + 0]);
                ffma2(av1, ep[k2], wE2[k2 * 4 + 1]);
                ffma2(av2, ep[k2], wE2[k2 * 4 + 2]);
                ffma2(av3, ep[k2], wE2[k2 * 4 + 3]);
            }
            acc.x = fmaf(fmaxf(fmaf(xj[u].x, a, fold2(av0)), 0.0f), vm[u], acc.x);
            acc.y = fmaf(fmaxf(fmaf(xj[u].y, a, fold2(av1)), 0.0f), vm[u], acc.y);
            acc.z = fmaf(fmaxf(fmaf(xj[u].z, a, fold2(av2)), 0.0f), vm[u], acc.z);
            acc.w = fmaf(fmaxf(fmaf(xj[u].w, a, fold2(av3)), 0.0f), vm[u], acc.w);
        }
    }

    // Rare overflow: degree > 32
#pragma unroll 1
    for (int j = beg + 32; j < end; j++) {
        const int s0 = __ldg(&esrc[j]);
        const float4 xj = *(const float4*)(h + (size_t)s0 * DD + d0);
        const float pj = __ldg(&pre[s0].y);
        const ulonglong2* ea = (const ulonglong2*)(ea_csr + (size_t)j * EDD);
        const ulonglong2 q0 = __ldg(ea + 0), q1 = __ldg(ea + 1),
                         q2 = __ldg(ea + 2), q3 = __ldg(ea + 3);
        const float a = 1.0f / (1.0f + __expf(-(pd + pj)));
        const unsigned long long ep[8] = {q0.x, q0.y, q1.x, q1.y,
                                          q2.x, q2.y, q3.x, q3.y};
        unsigned long long av0 = ebp[0], av1 = ebp[1], av2 = ebp[2], av3 = ebp[3];
#pragma unroll
        for (int k2 = 0; k2 < 8; k2++) {
            ffma2(av0, ep[k2], wE2[k2 * 4 + 0]);
            ffma2(av1, ep[k2], wE2[k2 * 4 + 1]);
            ffma2(av2, ep[k2], wE2[k2 * 4 + 2]);
            ffma2(av3, ep[k2], wE2[k2 * 4 + 3]);
        }
        acc.x += fmaxf(fmaf(xj.x, a, fold2(av0)), 0.0f);
        acc.y += fmaxf(fmaf(xj.y, a, fold2(av1)), 0.0f);
        acc.z += fmaxf(fmaf(xj.z, a, fold2(av2)), 0.0f);
        acc.w += fmaxf(fmaf(xj.w, a, fold2(av3)), 0.0f);
    }

    *(float4*)(agg + (size_t)node * DD + d0) = acc;
}

// ---------------------------------------------------------------------------
// SGEMM (identical to R7): 128 threads, 128x128 tile, 16x8 per-thread,
// scalar FFMA core, 4-stage cp.async(B) pipeline, one barrier per k-tile.
// ---------------------------------------------------------------------------
__global__ __launch_bounds__(128, 3)
void sgemm_kernel(const float* __restrict__ A, const float* __restrict__ B,
                  const float* __restrict__ bias,
                  const float* __restrict__ bn_g, const float* __restrict__ bn_b,
                  float* __restrict__ C,
                  int M, int K, int Nc, int do_relu, int do_bn) {
    __shared__ float As[4][8][128];   // [stage][k][row]
    __shared__ float Bs[4][8][128];   // [stage][k][col]

    const int tid = threadIdx.x;
    const int tx = tid & 15;
    const int ty = tid >> 4;
    const int row0 = blockIdx.y * 128;
    const int col0 = blockIdx.x * 128;

    const int a_row = tid >> 1;
    const int a_col = (tid & 1) * 4;
    const int b_row = tid >> 4;
    const int b_col = (tid & 15) * 8;

    const int gr1 = row0 + a_row, gr2 = gr1 + 64;
    const bool v1 = gr1 < M, v2 = gr2 < M;
    const float* aptr1 = A + (size_t)gr1 * K + a_col;
    const float* aptr2 = A + (size_t)gr2 * K + a_col;
    const float* bptr  = B + (size_t)b_row * Nc + col0 + b_col;

    const int nt = K >> 3;
    const float4 f40 = make_float4(0.f, 0.f, 0.f, 0.f);
    float4 ar0, ar1;

#define LDG_A(k0) { ar0 = v1 ? *(const float4*)(aptr1 + (k0)) : f40; \
                    ar1 = v2 ? *(const float4*)(aptr2 + (k0)) : f40; }
#define STS_A(stg) { As[stg][a_col+0][a_row] = ar0.x; As[stg][a_col+1][a_row] = ar0.y; \
                     As[stg][a_col+2][a_row] = ar0.z; As[stg][a_col+3][a_row] = ar0.w; \
                     As[stg][a_col+0][a_row+64] = ar1.x; As[stg][a_col+1][a_row+64] = ar1.y; \
                     As[stg][a_col+2][a_row+64] = ar1.z; As[stg][a_col+3][a_row+64] = ar1.w; }
#define CP_B(stg, k0) { \
    uint32_t _d = (uint32_t)__cvta_generic_to_shared(&Bs[stg][b_row][b_col]); \
    const float* _s = bptr + (size_t)(k0) * Nc; \
    asm volatile("cp.async.cg.shared.global [%0], [%1], 16;\n\t" \
                 "cp.async.cg.shared.global [%2], [%3], 16;\n\t" \
                 "cp.async.commit_group;\n" \
                 :: "r"(_d), "l"(_s), "r"(_d + 16), "l"(_s + 4) : "memory"); }

    float acc[16][8];
#pragma unroll
    for (int i = 0; i < 16; i++)
#pragma unroll
        for (int j = 0; j < 8; j++) acc[i][j] = 0.0f;

    // Prologue: tiles 0 and 1
    LDG_A(0); CP_B(0, 0); STS_A(0);
    LDG_A(8); CP_B(1, 8);

#pragma unroll 1
    for (int t = 0; t < nt; t++) {
        const int st = t & 3;
        if (t + 1 < nt) STS_A((t + 1) & 3);
        if (t + 2 < nt) { const int k0 = (t + 2) * 8; LDG_A(k0); CP_B((t + 2) & 3, k0); }
        const int rem = nt - 1 - t;
        if (rem >= 2)      asm volatile("cp.async.wait_group 2;" ::: "memory");
        else if (rem == 1) asm volatile("cp.async.wait_group 1;" ::: "memory");
        else               asm volatile("cp.async.wait_group 0;" ::: "memory");
        __syncthreads();

#pragma unroll
        for (int k = 0; k < 8; k++) {
            float af[16], bf[8];
            *(float4*)&af[0]  = *(const float4*)&As[st][k][ty * 16];
            *(float4*)&af[4]  = *(const float4*)&As[st][k][ty * 16 + 4];
            *(float4*)&af[8]  = *(const float4*)&As[st][k][ty * 16 + 8];
            *(float4*)&af[12] = *(const float4*)&As[st][k][ty * 16 + 12];
            *(float4*)&bf[0]  = *(const float4*)&Bs[st][k][tx * 8];
            *(float4*)&bf[4]  = *(const float4*)&Bs[st][k][tx * 8 + 4];
#pragma unroll
            for (int i = 0; i < 16; i++)
#pragma unroll
                for (int j = 0; j < 8; j++)
                    acc[i][j] = fmaf(af[i], bf[j], acc[i][j]);
        }
    }

    // Epilogue
    float bi[8], g[8], bb[8];
#pragma unroll
    for (int j = 0; j < 8; j++) {
        const int c = col0 + tx * 8 + j;
        bi[j] = bias[c];
        if (do_bn) { g[j] = bn_g[c]; bb[j] = bn_b[c]; }
    }
#pragma unroll
    for (int i = 0; i < 16; i++) {
        const int r = row0 + ty * 16 + i;
        if (r >= M) continue;
        float v[8];
#pragma unroll
        for (int j = 0; j < 8; j++) {
            float t = acc[i][j] + bi[j];
            if (do_bn) t = fmaf(g[j] * BN_INV, t, bb[j]);
            if (do_relu) t = fmaxf(t, 0.0f);
            v[j] = t;
        }
        float* cp = C + (size_t)r * Nc + col0 + tx * 8;
        *(float4*)cp       = make_float4(v[0], v[1], v[2], v[3]);
        *(float4*)(cp + 4) = make_float4(v[4], v[5], v[6], v[7]);
    }
#undef LDG_A
#undef STS_A
#undef CP_B
}

// ---------------------------------------------------------------------------
extern "C" void kernel_launch(void* const* d_in, const int* in_sizes, int n_in,
                              void* d_out, int out_size) {
    const float* x         = (const float*)d_in[0];
    const float* edge_attr = (const float*)d_in[1];
    const float* node_W    = (const float*)d_in[2];
    const float* node_b    = (const float*)d_in[3];
    const float* edge_W    = (const float*)d_in[4];
    const float* edge_b    = (const float*)d_in[5];
    const float* attn_W    = (const float*)d_in[6];
    const float* attn_b    = (const float*)d_in[7];
    const float* eps       = (const float*)d_in[8];
    const float* W1        = (const float*)d_in[9];
    const float* b1        = (const float*)d_in[10];
    const float* bn1_g     = (const float*)d_in[11];
    const float* bn1_b     = (const float*)d_in[12];
    const float* W2        = (const float*)d_in[13];
    const float* b2        = (const float*)d_in[14];
    const float* bn_g      = (const float*)d_in[15];
    const float* bn_b      = (const float*)d_in[16];
    const int*   edge_index= (const int*)d_in[17];

    float *hA, *hB, *agg, *tbuf, *ea_csr; float2* pre;
    int *deg, *off, *cur, *esrc;
    cudaGetSymbolAddress((void**)&hA,    g_h);
    cudaGetSymbolAddress((void**)&hB,    g_h2);
    cudaGetSymbolAddress((void**)&agg,   g_agg);
    cudaGetSymbolAddress((void**)&tbuf,  g_t);
    cudaGetSymbolAddress((void**)&pre,   g_pre);
    cudaGetSymbolAddress((void**)&deg,   g_deg);
    cudaGetSymbolAddress((void**)&off,   g_off);
    cudaGetSymbolAddress((void**)&cur,   g_cur);
    cudaGetSymbolAddress((void**)&esrc,  g_esrc);
    cudaGetSymbolAddress((void**)&ea_csr, g_ea);

    const int* src_arr = edge_index;
    const int* dst_arr = edge_index + EE;
    const int mblk = (NN + 127) / 128;     // 313

    // CSR build (deg zeroed via memset node)
    cudaMemsetAsync(deg, 0, NN * sizeof(int));
    count_kernel<<<(EE + 255) / 256, 256>>>(dst_arr, deg);
    scan_kernel<<<1, 1024>>>(deg, off, cur);
    fill_kernel<<<(EE + 255) / 256, 256>>>(src_arr, dst_arr, edge_attr,
                                           cur, esrc, ea_csr);

    // node encoder: h = x @ node_W + node_b
    sgemm_kernel<<<dim3(1, mblk), 128>>>(x, node_W, node_b, nullptr, nullptr,
                                         hA, NN, DD, DD, 0, 0);

    const float* hcur = hA;
    float* hnext = hB;
    for (int l = 0; l < LL; l++) {
        prep_kernel<<<10000, 128>>>(hcur, attn_W + (size_t)l * 2 * DD, pre);
        edge_csr_kernel<<<10000, 128>>>(hcur, ea_csr, off, esrc,
                                        edge_W + (size_t)l * EDD * DD,
                                        edge_b + (size_t)l * DD,
                                        pre, attn_b + l, eps + l, agg);
        // t = relu(bn1(agg @ W1 + b1))   [N,128]@[128,256]
        sgemm_kernel<<<dim3(2, mblk), 128>>>(agg, W1 + (size_t)l * DD * 2 * DD,
                                             b1 + (size_t)l * 2 * DD,
                                             bn1_g + (size_t)l * 2 * DD,
                                             bn1_b + (size_t)l * 2 * DD,
                                             tbuf, NN, DD, 2 * DD, 1, 1);
        // h' = [relu] bn(t @ W2 + b2)    [N,256]@[256,128]
        float* outp = (l == LL - 1) ? (float*)d_out : hnext;
        sgemm_kernel<<<dim3(1, mblk), 128>>>(tbuf, W2 + (size_t)l * 2 * DD * DD,
                                             b2 + (size_t)l * DD,
                                             bn_g + (size_t)l * DD,
                                             bn_b + (size_t)l * DD,
                                             outp, NN, 2 * DD, DD, (l < LL - 1) ? 1 : 0, 1);
        if (l < LL - 1) {
            hcur = outp;
            hnext = (outp == hA) ? hB : hA;
        }
    }
}

// round 12
// speedup vs baseline: 1.8595x; 1.1783x over previous
#include <cuda_runtime.h>
#include <cstdint>

// Problem constants
#define NN 40000
#define EE 640000
#define DD 128
#define EDD 16
#define LL 3
#define BN_INV 0.99999500003749978f  // 1/sqrt(1+1e-5)

// Scratch (no cudaMalloc allowed)
__device__ float  g_h[(size_t)NN * DD];
__device__ float  g_h2[(size_t)NN * DD];
__device__ float  g_agg[(size_t)NN * DD];
__device__ float  g_t[(size_t)NN * 2 * DD];
__device__ float2 g_pre[NN];
__device__ int    g_deg[NN];
__device__ int    g_off[NN + 1];
__device__ int    g_cur[NN];
__device__ int    g_esrc[EE];   // src node id per CSR slot
__device__ int    g_eidx[EE];   // original edge id per CSR slot

// ---- f32x2 helpers --------------------------------------------------------
__device__ __forceinline__ unsigned long long pack2(float lo, float hi) {
    unsigned long long r;
    asm("mov.b64 %0, {%1, %2};" : "=l"(r) : "f"(lo), "f"(hi));
    return r;
}
__device__ __forceinline__ void ffma2(unsigned long long& d,
                                      unsigned long long a,
                                      unsigned long long b) {
    asm("fma.rn.f32x2 %0, %1, %2, %0;" : "+l"(d) : "l"(a), "l"(b));
}
__device__ __forceinline__ void unpack2(unsigned long long v, float& lo, float& hi) {
    asm("mov.b64 {%0, %1}, %2;" : "=f"(lo), "=f"(hi) : "l"(v));
}
__device__ __forceinline__ float fold2(unsigned long long v) {
    float lo, hi; unpack2(v, lo, hi); return lo + hi;
}

// ---- tf32 helpers ---------------------------------------------------------
__device__ __forceinline__ void cvt_hilo(float raw, uint32_t& hi, uint32_t& lo) {
    asm("cvt.rna.tf32.f32 %0, %1;" : "=r"(hi) : "f"(raw));
    float rem = raw - __uint_as_float(hi);
    asm("cvt.rna.tf32.f32 %0, %1;" : "=r"(lo) : "f"(rem));
}
__device__ __forceinline__ void mma_tf32(float* d, const uint32_t* a,
                                         uint32_t b0, uint32_t b1) {
    asm volatile("mma.sync.aligned.m16n8k8.row.col.f32.tf32.tf32.f32 "
                 "{%0,%1,%2,%3}, {%4,%5,%6,%7}, {%8,%9}, {%0,%1,%2,%3};"
                 : "+f"(d[0]), "+f"(d[1]), "+f"(d[2]), "+f"(d[3])
                 : "r"(a[0]), "r"(a[1]), "r"(a[2]), "r"(a[3]),
                   "r"(b0), "r"(b1));
}

// ---------------------------------------------------------------------------
// CSR build (once per call): zero -> count -> scan -> fill   (R7 verbatim)
// ---------------------------------------------------------------------------
__global__ void zero_deg_kernel(int* __restrict__ deg) {
    int i = blockIdx.x * blockDim.x + threadIdx.x;
    if (i < NN) deg[i] = 0;
}

__global__ void count_kernel(const int* __restrict__ dst, int* __restrict__ deg) {
    int e = blockIdx.x * blockDim.x + threadIdx.x;
    if (e < EE) atomicAdd(&deg[dst[e]], 1);
}

__global__ __launch_bounds__(1024)
void scan_kernel(const int* __restrict__ deg, int* __restrict__ off,
                 int* __restrict__ cur) {
    __shared__ int part[1024];
    const int tid = threadIdx.x;
    const int per = (NN + 1023) / 1024;   // 40
    const int base = tid * per;
    int s = 0;
#pragma unroll 4
    for (int i = 0; i < per; i++) {
        const int n = base + i;
        if (n < NN) s += deg[n];
    }
    part[tid] = s;
    __syncthreads();
    for (int ofs = 1; ofs < 1024; ofs <<= 1) {
        int v = (tid >= ofs) ? part[tid - ofs] : 0;
        __syncthreads();
        part[tid] += v;
        __syncthreads();
    }
    int run = (tid > 0) ? part[tid - 1] : 0;   // exclusive prefix
    for (int i = 0; i < per; i++) {
        const int n = base + i;
        if (n < NN) {
            off[n] = run;
            cur[n] = run;
            run += deg[n];
        }
    }
    if (tid == 1023) off[NN] = EE;
}

__global__ void fill_kernel(const int* __restrict__ src,
                            const int* __restrict__ dst,
                            int* __restrict__ cur,
                            int* __restrict__ esrc,
                            int* __restrict__ eidx) {
    int e = blockIdx.x * blockDim.x + threadIdx.x;
    if (e >= EE) return;
    const int d = dst[e];
    const int p = atomicAdd(&cur[d], 1);
    esrc[p] = src[e];
    eidx[p] = e;
}

// ---------------------------------------------------------------------------
// prep: pre[n] = (h[n]·attn_W[0:128], h[n]·attn_W[128:256]). Warp per node.
// ---------------------------------------------------------------------------
__global__ __launch_bounds__(128)
void prep_kernel(const float* __restrict__ h,
                 const float* __restrict__ attn_W,   // [256]
                 float2* __restrict__ pre) {
    const int warp = (blockIdx.x * blockDim.x + threadIdx.x) >> 5;
    const int lane = threadIdx.x & 31;
    if (warp >= NN) return;
    const int d0 = lane * 4;
    const float4 hv = *(const float4*)(h + (size_t)warp * DD + d0);
    const float4 wi = *(const float4*)(attn_W + d0);
    const float4 wj = *(const float4*)(attn_W + DD + d0);
    float pi = hv.x * wi.x + hv.y * wi.y + hv.z * wi.z + hv.w * wi.w;
    float pj = hv.x * wj.x + hv.y * wj.y + hv.z * wj.z + hv.w * wj.w;
#pragma unroll
    for (int off = 16; off > 0; off >>= 1) {
        pi += __shfl_xor_sync(0xffffffffu, pi, off);
        pj += __shfl_xor_sync(0xffffffffu, pj, off);
    }
    if (lane == 0) pre[warp] = make_float2(pi, pj);
}

// ---------------------------------------------------------------------------
// per-edge accumulate helper (R7 verbatim)
// ---------------------------------------------------------------------------
__device__ __forceinline__ void accum_edge(
    float4& acc, float a, float vmask, const float4 xj,
    const ulonglong2 qa, const ulonglong2 qb,
    const ulonglong2 qc, const ulonglong2 qd,
    const unsigned long long* __restrict__ wE2,
    const unsigned long long* __restrict__ ebp) {
    const unsigned long long ep[8] = {qa.x, qa.y, qb.x, qb.y,
                                      qc.x, qc.y, qd.x, qd.y};
    unsigned long long av0 = ebp[0], av1 = ebp[1], av2 = ebp[2], av3 = ebp[3];
#pragma unroll
    for (int k2 = 0; k2 < 8; k2++) {
        ffma2(av0, ep[k2], wE2[k2 * 4 + 0]);
        ffma2(av1, ep[k2], wE2[k2 * 4 + 1]);
        ffma2(av2, ep[k2], wE2[k2 * 4 + 2]);
        ffma2(av3, ep[k2], wE2[k2 * 4 + 3]);
    }
    acc.x = fmaf(fmaxf(fmaf(xj.x, a, fold2(av0)), 0.0f), vmask, acc.x);
    acc.y = fmaf(fmaxf(fmaf(xj.y, a, fold2(av1)), 0.0f), vmask, acc.y);
    acc.z = fmaf(fmaxf(fmaf(xj.z, a, fold2(av2)), 0.0f), vmask, acc.z);
    acc.w = fmaf(fmaxf(fmaf(xj.w, a, fold2(av3)), 0.0f), vmask, acc.w);
}

// ---------------------------------------------------------------------------
// CSR edge kernel (R7 verbatim): warp per destination node, lane-vector
// index fetch, 4-edge load batches.
// ---------------------------------------------------------------------------
__global__ __launch_bounds__(128, 3)
void edge_csr_kernel(const float* __restrict__ h,
                     const float* __restrict__ edge_attr,
                     const int* __restrict__ off,
                     const int* __restrict__ esrc,
                     const int* __restrict__ eidx,
                     const float* __restrict__ edge_W,   // [16,128]
                     const float* __restrict__ edge_b,   // [128]
                     const float2* __restrict__ pre,     // [N]
                     const float* __restrict__ attn_b,   // [1]
                     const float* __restrict__ eps_l,
                     float* __restrict__ agg) {
    const int lane = threadIdx.x & 31;
    const int node = (blockIdx.x * blockDim.x + threadIdx.x) >> 5;
    if (node >= NN) return;
    const int d0 = lane * 4;

    unsigned long long wE2[32];
#pragma unroll
    for (int k2 = 0; k2 < 8; k2++) {
        const float4 wa = *(const float4*)(edge_W + (2 * k2) * DD + d0);
        const float4 wb = *(const float4*)(edge_W + (2 * k2 + 1) * DD + d0);
        wE2[k2 * 4 + 0] = pack2(wa.x, wb.x);
        wE2[k2 * 4 + 1] = pack2(wa.y, wb.y);
        wE2[k2 * 4 + 2] = pack2(wa.z, wb.z);
        wE2[k2 * 4 + 3] = pack2(wa.w, wb.w);
    }
    unsigned long long ebp[4];
    {
        const float4 eb = *(const float4*)(edge_b + d0);
        ebp[0] = pack2(eb.x, 0.0f); ebp[1] = pack2(eb.y, 0.0f);
        ebp[2] = pack2(eb.z, 0.0f); ebp[3] = pack2(eb.w, 0.0f);
    }
    const int beg = off[node], end = off[node + 1];
    const int deg = end - beg;
    const float pd = __ldg(&pre[node].x) + attn_b[0];

    float4 acc;
    {
        const float s = 1.0f + eps_l[0];
        const float4 hv = *(const float4*)(h + (size_t)node * DD + d0);
        acc.x = hv.x * s; acc.y = hv.y * s; acc.z = hv.z * s; acc.w = hv.w * s;
    }

    int j = beg;
    for (; j + 2 <= end; j += 2) {
        const int s0 = esrc[j],     s1 = esrc[j + 1];
        const int i0 = eidx[j],     i1 = eidx[j + 1];
        const float4 xj0 = *(const float4*)(h + (size_t)s0 * DD + d0);
        const float4 xj1 = *(const float4*)(h + (size_t)s1 * DD + d0);
        const float pj0 = __ldg(&pre[s0].y);
        const float pj1 = __ldg(&pre[s1].y);
        const ulonglong2* ea0 = (const ulonglong2*)(edge_attr + (size_t)i0 * EDD);
        const ulonglong2* ea1 = (const ulonglong2*)(edge_attr + (size_t)i1 * EDD);
        const ulonglong2 q00 = __ldg(ea0 + 0), q01 = __ldg(ea0 + 1),
                         q02 = __ldg(ea0 + 2), q03 = __ldg(ea0 + 3);
        const ulonglong2 q10 = __ldg(ea1 + 0), q11 = __ldg(ea1 + 1),
                         q12 = __ldg(ea1 + 2), q13 = __ldg(ea1 + 3);
        const float a0 = 1.0f / (1.0f + __expf(-(pd + pj0)));
        const float a1 = 1.0f / (1.0f + __expf(-(pd + pj1)));
        accum_edge(acc, a0, 1.0f, xj0, q00, q01, q02, q03, wE2, ebp);
        accum_edge(acc, a1, 1.0f, xj1, q10, q11, q12, q13, wE2, ebp);
    }
    if (j < end) {
        const int s0 = esrc[j];
        const int i0 = eidx[j];
        const float4 xj0 = *(const float4*)(h + (size_t)s0 * DD + d0);
        const float pj0 = __ldg(&pre[s0].y);
        const ulonglong2* ea0 = (const ulonglong2*)(edge_attr + (size_t)i0 * EDD);
        const ulonglong2 q00 = __ldg(ea0 + 0), q01 = __ldg(ea0 + 1),
                         q02 = __ldg(ea0 + 2), q03 = __ldg(ea0 + 3);
        const float a0 = 1.0f / (1.0f + __expf(-(pd + pj0)));
        accum_edge(acc, a0, 1.0f, xj0, q00, q01, q02, q03, wE2, ebp);
    }

    *(float4*)(agg + (size_t)node * DD + d0) = acc;
}

// ---------------------------------------------------------------------------
// 3xTF32 tensor-core GEMM: 256 threads, 128x128 CTA tile, warp tile 32x64
// (2x8 m16n8k8 tiles), 4-stage cp.async(B)/STS(A) pipeline (R7 structure),
// smem rows padded to 136 for conflict-free fragment LDS.
// acc = Ahi@Bhi + Ahi@Blo + Alo@Bhi  (fp32-class precision)
// ---------------------------------------------------------------------------
__global__ __launch_bounds__(256, 2)
void tgemm_kernel(const float* __restrict__ A, const float* __restrict__ B,
                  const float* __restrict__ bias,
                  const float* __restrict__ bn_g, const float* __restrict__ bn_b,
                  float* __restrict__ C,
                  int M, int K, int Nc, int do_relu, int do_bn) {
    __shared__ __align__(16) float As[4][8][136];   // [stage][k][row(+pad)]
    __shared__ __align__(16) float Bs[4][8][136];   // [stage][k][col(+pad)]

    const int tid = threadIdx.x;
    const int wid = tid >> 5;
    const int lane = tid & 31;
    const int gID = lane >> 2;       // 0..7
    const int tIG = lane & 3;        // 0..3
    const int warp_m = wid >> 1;     // 0..3  (32 rows each)
    const int warp_n = wid & 1;      // 0..1  (64 cols each)
    const int row0 = blockIdx.y * 128;
    const int col0 = blockIdx.x * 128;

    // staging indices
    const int a_row = tid >> 1;           // 0..127
    const int a_col = (tid & 1) * 4;      // 0 or 4
    const int b_row = tid >> 5;           // 0..7
    const int b_col = lane * 4;           // 0..124

    const int gr = row0 + a_row;
    const bool av = gr < M;
    const float* aptr = A + (size_t)gr * K + a_col;
    const float* bptr = B + (size_t)b_row * Nc + col0 + b_col;

    const int nt = K >> 3;
    const float4 f40 = make_float4(0.f, 0.f, 0.f, 0.f);
    float4 ar;

#define LDG_A(k0) { ar = av ? *(const float4*)(aptr + (k0)) : f40; }
#define STS_A(stg) { As[stg][a_col+0][a_row] = ar.x; As[stg][a_col+1][a_row] = ar.y; \
                     As[stg][a_col+2][a_row] = ar.z; As[stg][a_col+3][a_row] = ar.w; }
#define CP_B(stg, k0) { \
    uint32_t _d = (uint32_t)__cvta_generic_to_shared(&Bs[stg][b_row][b_col]); \
    const float* _s = bptr + (size_t)(k0) * Nc; \
    asm volatile("cp.async.cg.shared.global [%0], [%1], 16;\n\t" \
                 "cp.async.commit_group;\n" \
                 :: "r"(_d), "l"(_s) : "memory"); }

    float acc[2][8][4];
#pragma unroll
    for (int i = 0; i < 2; i++)
#pragma unroll
        for (int jj = 0; jj < 8; jj++)
#pragma unroll
            for (int c = 0; c < 4; c++) acc[i][jj][c] = 0.0f;

    // Prologue: tiles 0 and 1
    LDG_A(0); CP_B(0, 0); STS_A(0);
    LDG_A(8); CP_B(1, 8);

#pragma unroll 1
    for (int t = 0; t < nt; t++) {
        const int st = t & 3;
        if (t + 1 < nt) STS_A((t + 1) & 3);
        if (t + 2 < nt) { const int k0 = (t + 2) * 8; LDG_A(k0); CP_B((t + 2) & 3, k0); }
        const int rem = nt - 1 - t;
        if (rem >= 2)      asm volatile("cp.async.wait_group 2;" ::: "memory");
        else if (rem == 1) asm volatile("cp.async.wait_group 1;" ::: "memory");
        else               asm volatile("cp.async.wait_group 0;" ::: "memory");
        __syncthreads();

        // A fragments for both 16-row tiles of this warp (hi/lo)
        uint32_t Ah[2][4], Al[2][4];
#pragma unroll
        for (int i = 0; i < 2; i++) {
            const int rb = warp_m * 32 + i * 16 + gID;
            const float r0 = As[st][tIG    ][rb];
            const float r1 = As[st][tIG    ][rb + 8];
            const float r2 = As[st][tIG + 4][rb];
            const float r3 = As[st][tIG + 4][rb + 8];
            cvt_hilo(r0, Ah[i][0], Al[i][0]);
            cvt_hilo(r1, Ah[i][1], Al[i][1]);
            cvt_hilo(r2, Ah[i][2], Al[i][2]);
            cvt_hilo(r3, Ah[i][3], Al[i][3]);
        }
#pragma unroll
        for (int jn = 0; jn < 8; jn++) {
            const int cb = warp_n * 64 + jn * 8 + gID;
            const float q0 = Bs[st][tIG    ][cb];
            const float q1 = Bs[st][tIG + 4][cb];
            uint32_t bh0, bl0, bh1, bl1;
            cvt_hilo(q0, bh0, bl0);
            cvt_hilo(q1, bh1, bl1);
#pragma unroll
            for (int i = 0; i < 2; i++) {
                mma_tf32(acc[i][jn], Ah[i], bh0, bh1);
                mma_tf32(acc[i][jn], Ah[i], bl0, bl1);
                mma_tf32(acc[i][jn], Al[i], bh0, bh1);
            }
        }
    }

    // Epilogue: each lane owns rows {gID, gID+8} and cols {2tIG, 2tIG+1}
    // of each (i, jn) tile.
#pragma unroll
    for (int i = 0; i < 2; i++) {
        const int r_lo = row0 + warp_m * 32 + i * 16 + gID;
        const int r_hi = r_lo + 8;
#pragma unroll
        for (int jn = 0; jn < 8; jn++) {
            const int c = col0 + warp_n * 64 + jn * 8 + tIG * 2;
            const float b0v = bias[c], b1v = bias[c + 1];
            float v00 = acc[i][jn][0] + b0v;
            float v01 = acc[i][jn][1] + b1v;
            float v10 = acc[i][jn][2] + b0v;
            float v11 = acc[i][jn][3] + b1v;
            if (do_bn) {
                const float g0 = bn_g[c] * BN_INV, g1 = bn_g[c + 1] * BN_INV;
                const float bb0 = bn_b[c], bb1 = bn_b[c + 1];
                v00 = fmaf(g0, v00, bb0); v01 = fmaf(g1, v01, bb1);
                v10 = fmaf(g0, v10, bb0); v11 = fmaf(g1, v11, bb1);
            }
            if (do_relu) {
                v00 = fmaxf(v00, 0.0f); v01 = fmaxf(v01, 0.0f);
                v10 = fmaxf(v10, 0.0f); v11 = fmaxf(v11, 0.0f);
            }
            if (r_lo < M) *(float2*)(C + (size_t)r_lo * Nc + c) = make_float2(v00, v01);
            if (r_hi < M) *(float2*)(C + (size_t)r_hi * Nc + c) = make_float2(v10, v11);
        }
    }
#undef LDG_A
#undef STS_A
#undef CP_B
}

// ---------------------------------------------------------------------------
extern "C" void kernel_launch(void* const* d_in, const int* in_sizes, int n_in,
                              void* d_out, int out_size) {
    const float* x         = (const float*)d_in[0];
    const float* edge_attr = (const float*)d_in[1];
    const float* node_W    = (const float*)d_in[2];
    const float* node_b    = (const float*)d_in[3];
    const float* edge_W    = (const float*)d_in[4];
    const float* edge_b    = (const float*)d_in[5];
    const float* attn_W    = (const float*)d_in[6];
    const float* attn_b    = (const float*)d_in[7];
    const float* eps       = (const float*)d_in[8];
    const float* W1        = (const float*)d_in[9];
    const float* b1        = (const float*)d_in[10];
    const float* bn1_g     = (const float*)d_in[11];
    const float* bn1_b     = (const float*)d_in[12];
    const float* W2        = (const float*)d_in[13];
    const float* b2        = (const float*)d_in[14];
    const float* bn_g      = (const float*)d_in[15];
    const float* bn_b      = (const float*)d_in[16];
    const int*   edge_index= (const int*)d_in[17];

    float *hA, *hB, *agg, *tbuf; float2* pre;
    int *deg, *off, *cur, *esrc, *eidx;
    cudaGetSymbolAddress((void**)&hA,   g_h);
    cudaGetSymbolAddress((void**)&hB,   g_h2);
    cudaGetSymbolAddress((void**)&agg,  g_agg);
    cudaGetSymbolAddress((void**)&tbuf, g_t);
    cudaGetSymbolAddress((void**)&pre,  g_pre);
    cudaGetSymbolAddress((void**)&deg,  g_deg);
    cudaGetSymbolAddress((void**)&off,  g_off);
    cudaGetSymbolAddress((void**)&cur,  g_cur);
    cudaGetSymbolAddress((void**)&esrc, g_esrc);
    cudaGetSymbolAddress((void**)&eidx, g_eidx);

    const int* src_arr = edge_index;
    const int* dst_arr = edge_index + EE;
    const int mblk = (NN + 127) / 128;     // 313

    // CSR build
    zero_deg_kernel<<<(NN + 255) / 256, 256>>>(deg);
    count_kernel<<<(EE + 255) / 256, 256>>>(dst_arr, deg);
    scan_kernel<<<1, 1024>>>(deg, off, cur);
    fill_kernel<<<(EE + 255) / 256, 256>>>(src_arr, dst_arr, cur, esrc, eidx);

    // node encoder: h = x @ node_W + node_b
    tgemm_kernel<<<dim3(1, mblk), 256>>>(x, node_W, node_b, nullptr, nullptr,
                                         hA, NN, DD, DD, 0, 0);

    const float* hcur = hA;
    float* hnext = hB;
    for (int l = 0; l < LL; l++) {
        prep_kernel<<<10000, 128>>>(hcur, attn_W + (size_t)l * 2 * DD, pre);
        edge_csr_kernel<<<10000, 128>>>(hcur, edge_attr, off, esrc, eidx,
                                        edge_W + (size_t)l * EDD * DD,
                                        edge_b + (size_t)l * DD,
                                        pre, attn_b + l, eps + l, agg);
        // t = relu(bn1(agg @ W1 + b1))   [N,128]@[128,256]
        tgemm_kernel<<<dim3(2, mblk), 256>>>(agg, W1 + (size_t)l * DD * 2 * DD,
                                             b1 + (size_t)l * 2 * DD,
                                             bn1_g + (size_t)l * 2 * DD,
                                             bn1_b + (size_t)l * 2 * DD,
                                             tbuf, NN, DD, 2 * DD, 1, 1);
        // h' = [relu] bn(t @ W2 + b2)    [N,256]@[256,128]
        float* outp = (l == LL - 1) ? (float*)d_out : hnext;
        tgemm_kernel<<<dim3(1, mblk), 256>>>(tbuf, W2 + (size_t)l * 2 * DD * DD,
                                             b2 + (size_t)l * DD,
                                             bn_g + (size_t)l * DD,
                                             bn_b + (size_t)l * DD,
                                             outp, NN, 2 * DD, DD, (l < LL - 1) ? 1 : 0, 1);
        if (l < LL - 1) {
            hcur = outp;
            hnext = (outp == hA) ? hB : hA;
        }
    }
}

// round 14
// speedup vs baseline: 1.8905x; 1.0167x over previous
#include <cuda_runtime.h>
#include <cstdint>

// Problem constants
#define NN 40000
#define EE 640000
#define DD 128
#define EDD 16
#define LL 3
#define BN_INV 0.99999500003749978f  // 1/sqrt(1+1e-5)

// Scratch (no cudaMalloc allowed)
__device__ float  g_h[(size_t)NN * DD];
__device__ float  g_h2[(size_t)NN * DD];
__device__ float  g_agg[(size_t)NN * DD];
__device__ float  g_t[(size_t)NN * 2 * DD];
__device__ float2 g_pre[NN];
__device__ int    g_deg[NN];
__device__ int    g_off[NN + 1];
__device__ int    g_cur[NN];
__device__ int    g_esrc[EE];   // src node id per CSR slot
__device__ int    g_eidx[EE];   // original edge id per CSR slot
// tf32 hi/lo split of all GEMM weights:
//  [0, 16384)              node_W   (K=128, N=128)
//  [16384, 114688)         W1[3]    (K=128, N=256) each 32768
//  [114688, 212992)        W2[3]    (K=256, N=128) each 32768
#define WSPLIT_TOTAL 212992
__device__ float g_whi[WSPLIT_TOTAL];
__device__ float g_wlo[WSPLIT_TOTAL];

// ---- f32x2 helpers --------------------------------------------------------
__device__ __forceinline__ unsigned long long pack2(float lo, float hi) {
    unsigned long long r;
    asm("mov.b64 %0, {%1, %2};" : "=l"(r) : "f"(lo), "f"(hi));
    return r;
}
__device__ __forceinline__ void ffma2(unsigned long long& d,
                                      unsigned long long a,
                                      unsigned long long b) {
    asm("fma.rn.f32x2 %0, %1, %2, %0;" : "+l"(d) : "l"(a), "l"(b));
}
__device__ __forceinline__ void unpack2(unsigned long long v, float& lo, float& hi) {
    asm("mov.b64 {%0, %1}, %2;" : "=f"(lo), "=f"(hi) : "l"(v));
}
__device__ __forceinline__ float fold2(unsigned long long v) {
    float lo, hi; unpack2(v, lo, hi); return lo + hi;
}

// ---- tf32 helpers ---------------------------------------------------------
__device__ __forceinline__ void cvt_hilo(float raw, uint32_t& hi, uint32_t& lo) {
    asm("cvt.rna.tf32.f32 %0, %1;" : "=r"(hi) : "f"(raw));
    float rem = raw - __uint_as_float(hi);
    asm("cvt.rna.tf32.f32 %0, %1;" : "=r"(lo) : "f"(rem));
}
__device__ __forceinline__ void mma_tf32(float* d, const uint32_t* a,
                                         uint32_t b0, uint32_t b1) {
    asm volatile("mma.sync.aligned.m16n8k8.row.col.f32.tf32.tf32.f32 "
                 "{%0,%1,%2,%3}, {%4,%5,%6,%7}, {%8,%9}, {%0,%1,%2,%3};"
                 : "+f"(d[0]), "+f"(d[1]), "+f"(d[2]), "+f"(d[3])
                 : "r"(a[0]), "r"(a[1]), "r"(a[2]), "r"(a[3]),
                   "r"(b0), "r"(b1));
}

// ---------------------------------------------------------------------------
// weight split: hi = tf32(w), lo = tf32(w - hi)
// ---------------------------------------------------------------------------
__global__ void wsplit_kernel(const float* __restrict__ w,
                              float* __restrict__ whi,
                              float* __restrict__ wlo, int n) {
    int i = blockIdx.x * blockDim.x + threadIdx.x;
    if (i >= n) return;
    uint32_t hi, lo;
    cvt_hilo(w[i], hi, lo);
    whi[i] = __uint_as_float(hi);
    wlo[i] = __uint_as_float(lo);
}

// ---------------------------------------------------------------------------
// CSR build (once per call): zero -> count -> scan -> fill
// ---------------------------------------------------------------------------
__global__ void zero_deg_kernel(int* __restrict__ deg) {
    int i = blockIdx.x * blockDim.x + threadIdx.x;
    if (i < NN) deg[i] = 0;
}

__global__ void count_kernel(const int* __restrict__ dst, int* __restrict__ deg) {
    int e = blockIdx.x * blockDim.x + threadIdx.x;
    if (e < EE) atomicAdd(&deg[dst[e]], 1);
}

__global__ __launch_bounds__(1024)
void scan_kernel(const int* __restrict__ deg, int* __restrict__ off,
                 int* __restrict__ cur) {
    __shared__ int part[1024];
    const int tid = threadIdx.x;
    const int per = (NN + 1023) / 1024;   // 40
    const int base = tid * per;
    int s = 0;
#pragma unroll 4
    for (int i = 0; i < per; i++) {
        const int n = base + i;
        if (n < NN) s += deg[n];
    }
    part[tid] = s;
    __syncthreads();
    for (int ofs = 1; ofs < 1024; ofs <<= 1) {
        int v = (tid >= ofs) ? part[tid - ofs] : 0;
        __syncthreads();
        part[tid] += v;
        __syncthreads();
    }
    int run = (tid > 0) ? part[tid - 1] : 0;   // exclusive prefix
    for (int i = 0; i < per; i++) {
        const int n = base + i;
        if (n < NN) {
            off[n] = run;
            cur[n] = run;
            run += deg[n];
        }
    }
    if (tid == 1023) off[NN] = EE;
}

__global__ void fill_kernel(const int* __restrict__ src,
                            const int* __restrict__ dst,
                            int* __restrict__ cur,
                            int* __restrict__ esrc,
                            int* __restrict__ eidx) {
    int e = blockIdx.x * blockDim.x + threadIdx.x;
    if (e >= EE) return;
    const int d = dst[e];
    const int p = atomicAdd(&cur[d], 1);
    esrc[p] = src[e];
    eidx[p] = e;
}

// ---------------------------------------------------------------------------
// prep: pre[n] = (h[n]·attn_W[0:128], h[n]·attn_W[128:256]). Warp per node.
// ---------------------------------------------------------------------------
__global__ __launch_bounds__(128)
void prep_kernel(const float* __restrict__ h,
                 const float* __restrict__ attn_W,   // [256]
                 float2* __restrict__ pre) {
    const int warp = (blockIdx.x * blockDim.x + threadIdx.x) >> 5;
    const int lane = threadIdx.x & 31;
    if (warp >= NN) return;
    const int d0 = lane * 4;
    const float4 hv = *(const float4*)(h + (size_t)warp * DD + d0);
    const float4 wi = *(const float4*)(attn_W + d0);
    const float4 wj = *(const float4*)(attn_W + DD + d0);
    float pi = hv.x * wi.x + hv.y * wi.y + hv.z * wi.z + hv.w * wi.w;
    float pj = hv.x * wj.x + hv.y * wj.y + hv.z * wj.z + hv.w * wj.w;
#pragma unroll
    for (int off = 16; off > 0; off >>= 1) {
        pi += __shfl_xor_sync(0xffffffffu, pi, off);
        pj += __shfl_xor_sync(0xffffffffu, pj, off);
    }
    if (lane == 0) pre[warp] = make_float2(pi, pj);
}

// ---------------------------------------------------------------------------
// per-edge accumulate helper
// ---------------------------------------------------------------------------
__device__ __forceinline__ void accum_edge(
    float4& acc, float a, const float4 xj,
    const ulonglong2 qa, const ulonglong2 qb,
    const ulonglong2 qc, const ulonglong2 qd,
    const unsigned long long* __restrict__ wE2,
    const unsigned long long* __restrict__ ebp) {
    const unsigned long long ep[8] = {qa.x, qa.y, qb.x, qb.y,
                                      qc.x, qc.y, qd.x, qd.y};
    unsigned long long av0 = ebp[0], av1 = ebp[1], av2 = ebp[2], av3 = ebp[3];
#pragma unroll
    for (int k2 = 0; k2 < 8; k2++) {
        ffma2(av0, ep[k2], wE2[k2 * 4 + 0]);
        ffma2(av1, ep[k2], wE2[k2 * 4 + 1]);
        ffma2(av2, ep[k2], wE2[k2 * 4 + 2]);
        ffma2(av3, ep[k2], wE2[k2 * 4 + 3]);
    }
    acc.x += fmaxf(fmaf(xj.x, a, fold2(av0)), 0.0f);
    acc.y += fmaxf(fmaf(xj.y, a, fold2(av1)), 0.0f);
    acc.z += fmaxf(fmaf(xj.z, a, fold2(av2)), 0.0f);
    acc.w += fmaxf(fmaf(xj.w, a, fold2(av3)), 0.0f);
}

// ---------------------------------------------------------------------------
// CSR edge kernel (R7 inner body), PERSISTENT: warp grid-strides over nodes,
// weight prologue runs once per warp. Grid = 444 CTAs (3/SM), no wave churn.
// ---------------------------------------------------------------------------
__global__ __launch_bounds__(128, 3)
void edge_csr_kernel(const float* __restrict__ h,
                     const float* __restrict__ edge_attr,
                     const int* __restrict__ off,
                     const int* __restrict__ esrc,
                     const int* __restrict__ eidx,
                     const float* __restrict__ edge_W,   // [16,128]
                     const float* __restrict__ edge_b,   // [128]
                     const float2* __restrict__ pre,     // [N]
                     const float* __restrict__ attn_b,   // [1]
                     const float* __restrict__ eps_l,
                     float* __restrict__ agg) {
    const int lane = threadIdx.x & 31;
    const int gwarp = (blockIdx.x * blockDim.x + threadIdx.x) >> 5;
    const int nwarp = (gridDim.x * blockDim.x) >> 5;
    const int d0 = lane * 4;

    unsigned long long wE2[32];
#pragma unroll
    for (int k2 = 0; k2 < 8; k2++) {
        const float4 wa = *(const float4*)(edge_W + (2 * k2) * DD + d0);
        const float4 wb = *(const float4*)(edge_W + (2 * k2 + 1) * DD + d0);
        wE2[k2 * 4 + 0] = pack2(wa.x, wb.x);
        wE2[k2 * 4 + 1] = pack2(wa.y, wb.y);
        wE2[k2 * 4 + 2] = pack2(wa.z, wb.z);
        wE2[k2 * 4 + 3] = pack2(wa.w, wb.w);
    }
    unsigned long long ebp[4];
    {
        const float4 eb = *(const float4*)(edge_b + d0);
        ebp[0] = pack2(eb.x, 0.0f); ebp[1] = pack2(eb.y, 0.0f);
        ebp[2] = pack2(eb.z, 0.0f); ebp[3] = pack2(eb.w, 0.0f);
    }
    const float ab = attn_b[0];
    const float s = 1.0f + eps_l[0];

#pragma unroll 1
    for (int node = gwarp; node < NN; node += nwarp) {
        const int beg = off[node], end = off[node + 1];
        const float pd = __ldg(&pre[node].x) + ab;

        float4 acc;
        {
            const float4 hv = *(const float4*)(h + (size_t)node * DD + d0);
            acc.x = hv.x * s; acc.y = hv.y * s; acc.z = hv.z * s; acc.w = hv.w * s;
        }

        int j = beg;
        for (; j + 2 <= end; j += 2) {
            const int s0 = esrc[j],     s1 = esrc[j + 1];
            const int i0 = eidx[j],     i1 = eidx[j + 1];
            const float4 xj0 = *(const float4*)(h + (size_t)s0 * DD + d0);
            const float4 xj1 = *(const float4*)(h + (size_t)s1 * DD + d0);
            const float pj0 = __ldg(&pre[s0].y);
            const float pj1 = __ldg(&pre[s1].y);
            const ulonglong2* ea0 = (const ulonglong2*)(edge_attr + (size_t)i0 * EDD);
            const ulonglong2* ea1 = (const ulonglong2*)(edge_attr + (size_t)i1 * EDD);
            const ulonglong2 q00 = __ldg(ea0 + 0), q01 = __ldg(ea0 + 1),
                             q02 = __ldg(ea0 + 2), q03 = __ldg(ea0 + 3);
            const ulonglong2 q10 = __ldg(ea1 + 0), q11 = __ldg(ea1 + 1),
                             q12 = __ldg(ea1 + 2), q13 = __ldg(ea1 + 3);
            const float a0 = 1.0f / (1.0f + __expf(-(pd + pj0)));
            const float a1 = 1.0f / (1.0f + __expf(-(pd + pj1)));
            accum_edge(acc, a0, xj0, q00, q01, q02, q03, wE2, ebp);
            accum_edge(acc, a1, xj1, q10, q11, q12, q13, wE2, ebp);
        }
        if (j < end) {
            const int s0 = esrc[j];
            const int i0 = eidx[j];
            const float4 xj0 = *(const float4*)(h + (size_t)s0 * DD + d0);
            const float pj0 = __ldg(&pre[s0].y);
            const ulonglong2* ea0 = (const ulonglong2*)(edge_attr + (size_t)i0 * EDD);
            const ulonglong2 q00 = __ldg(ea0 + 0), q01 = __ldg(ea0 + 1),
                             q02 = __ldg(ea0 + 2), q03 = __ldg(ea0 + 3);
            const float a0 = 1.0f / (1.0f + __expf(-(pd + pj0)));
            accum_edge(acc, a0, xj0, q00, q01, q02, q03, wE2, ebp);
        }

        *(float4*)(agg + (size_t)node * DD + d0) = acc;
    }
}

// ---------------------------------------------------------------------------
// 3xTF32 tensor-core GEMM v2: B pre-split into tf32 hi/lo (no B cvt in-loop).
// 256 threads, 128x128 CTA tile, warp tile 32x64 (2x8 m16n8k8 tiles).
// A ring: 3 stages (STS distance 1, barrier-ordered). B rings: 4 stages
// (cp.async distance 2). smem rows padded to 136 for conflict-free LDS.
// ---------------------------------------------------------------------------
__global__ __launch_bounds__(256, 2)
void tgemm_kernel(const float* __restrict__ A,
                  const float* __restrict__ Bhi, const float* __restrict__ Blo,
                  const float* __restrict__ bias,
                  const float* __restrict__ bn_g, const float* __restrict__ bn_b,
                  float* __restrict__ C,
                  int M, int K, int Nc, int do_relu, int do_bn) {
    __shared__ __align__(16) float As[3][8][136];
    __shared__ __align__(16) float Bh[4][8][136];
    __shared__ __align__(16) float Bl[4][8][136];

    const int tid = threadIdx.x;
    const int wid = tid >> 5;
    const int lane = tid & 31;
    const int gID = lane >> 2;       // 0..7
    const int tIG = lane & 3;        // 0..3
    const int warp_m = wid >> 1;     // 0..3  (32 rows each)
    const int warp_n = wid & 1;      // 0..1  (64 cols each)
    const int row0 = blockIdx.y * 128;
    const int col0 = blockIdx.x * 128;

    const int a_row = tid >> 1;           // 0..127
    const int a_col = (tid & 1) * 4;      // 0 or 4
    const int b_row = tid >> 5;           // 0..7
    const int b_col = lane * 4;           // 0..124

    const int gr = row0 + a_row;
    const bool av = gr < M;
    const float* aptr  = A   + (size_t)gr * K + a_col;
    const float* bhptr = Bhi + (size_t)b_row * Nc + col0 + b_col;
    const float* blptr = Blo + (size_t)b_row * Nc + col0 + b_col;

    const int nt = K >> 3;
    const float4 f40 = make_float4(0.f, 0.f, 0.f, 0.f);
    float4 ar;

#define LDG_A(k0) { ar = av ? *(const float4*)(aptr + (k0)) : f40; }
#define STS_A(stg) { As[stg][a_col+0][a_row] = ar.x; As[stg][a_col+1][a_row] = ar.y; \
                     As[stg][a_col+2][a_row] = ar.z; As[stg][a_col+3][a_row] = ar.w; }
#define CP_B(stg, k0) { \
    uint32_t _dh = (uint32_t)__cvta_generic_to_shared(&Bh[stg][b_row][b_col]); \
    uint32_t _dl = (uint32_t)__cvta_generic_to_shared(&Bl[stg][b_row][b_col]); \
    const float* _sh = bhptr + (size_t)(k0) * Nc; \
    const float* _sl = blptr + (size_t)(k0) * Nc; \
    asm volatile("cp.async.cg.shared.global [%0], [%1], 16;\n\t" \
                 "cp.async.cg.shared.global [%2], [%3], 16;\n\t" \
                 "cp.async.commit_group;\n" \
                 :: "r"(_dh), "l"(_sh), "r"(_dl), "l"(_sl) : "memory"); }

    float acc[2][8][4];
#pragma unroll
    for (int i = 0; i < 2; i++)
#pragma unroll
        for (int jj = 0; jj < 8; jj++)
#pragma unroll
            for (int c = 0; c < 4; c++) acc[i][jj][c] = 0.0f;

    // Prologue: tiles 0 and 1
    LDG_A(0); CP_B(0, 0); STS_A(0);
    LDG_A(8); CP_B(1, 8);

#pragma unroll 1
    for (int t = 0; t < nt; t++) {
        const int sa = t % 3;        // A stage
        const int sb = t & 3;        // B stage
        if (t + 1 < nt) STS_A((t + 1) % 3);
        if (t + 2 < nt) { const int k0 = (t + 2) * 8; LDG_A(k0); CP_B((t + 2) & 3, k0); }
        const int rem = nt - 1 - t;
        if (rem >= 2)      asm volatile("cp.async.wait_group 2;" ::: "memory");
        else if (rem == 1) asm volatile("cp.async.wait_group 1;" ::: "memory");
        else               asm volatile("cp.async.wait_group 0;" ::: "memory");
        __syncthreads();

        // A fragments (hi/lo) for both 16-row tiles of this warp
        uint32_t Ah[2][4], Al[2][4];
#pragma unroll
        for (int i = 0; i < 2; i++) {
            const int rb = warp_m * 32 + i * 16 + gID;
            const float r0 = As[sa][tIG    ][rb];
            const float r1 = As[sa][tIG    ][rb + 8];
            const float r2 = As[sa][tIG + 4][rb];
            const float r3 = As[sa][tIG + 4][rb + 8];
            cvt_hilo(r0, Ah[i][0], Al[i][0]);
            cvt_hilo(r1, Ah[i][1], Al[i][1]);
            cvt_hilo(r2, Ah[i][2], Al[i][2]);
            cvt_hilo(r3, Ah[i][3], Al[i][3]);
        }
#pragma unroll
        for (int jn = 0; jn < 8; jn++) {
            const int cb = warp_n * 64 + jn * 8 + gID;
            const uint32_t bh0 = __float_as_uint(Bh[sb][tIG    ][cb]);
            const uint32_t bh1 = __float_as_uint(Bh[sb][tIG + 4][cb]);
            const uint32_t bl0 = __float_as_uint(Bl[sb][tIG    ][cb]);
            const uint32_t bl1 = __float_as_uint(Bl[sb][tIG + 4][cb]);
#pragma unroll
            for (int i = 0; i < 2; i++) {
                mma_tf32(acc[i][jn], Ah[i], bh0, bh1);
                mma_tf32(acc[i][jn], Ah[i], bl0, bl1);
                mma_tf32(acc[i][jn], Al[i], bh0, bh1);
            }
        }
    }

    // Epilogue: lane owns rows {gID, gID+8}, cols {2tIG, 2tIG+1} per tile.
#pragma unroll
    for (int i = 0; i < 2; i++) {
        const int r_lo = row0 + warp_m * 32 + i * 16 + gID;
        const int r_hi = r_lo + 8;
#pragma unroll
        for (int jn = 0; jn < 8; jn++) {
            const int c = col0 + warp_n * 64 + jn * 8 + tIG * 2;
            const float b0v = bias[c], b1v = bias[c + 1];
            float v00 = acc[i][jn][0] + b0v;
            float v01 = acc[i][jn][1] + b1v;
            float v10 = acc[i][jn][2] + b0v;
            float v11 = acc[i][jn][3] + b1v;
            if (do_bn) {
                const float g0 = bn_g[c] * BN_INV, g1 = bn_g[c + 1] * BN_INV;
                const float bb0 = bn_b[c], bb1 = bn_b[c + 1];
                v00 = fmaf(g0, v00, bb0); v01 = fmaf(g1, v01, bb1);
                v10 = fmaf(g0, v10, bb0); v11 = fmaf(g1, v11, bb1);
            }
            if (do_relu) {
                v00 = fmaxf(v00, 0.0f); v01 = fmaxf(v01, 0.0f);
                v10 = fmaxf(v10, 0.0f); v11 = fmaxf(v11, 0.0f);
            }
            if (r_lo < M) *(float2*)(C + (size_t)r_lo * Nc + c) = make_float2(v00, v01);
            if (r_hi < M) *(float2*)(C + (size_t)r_hi * Nc + c) = make_float2(v10, v11);
        }
    }
#undef LDG_A
#undef STS_A
#undef CP_B
}

// ---------------------------------------------------------------------------
extern "C" void kernel_launch(void* const* d_in, const int* in_sizes, int n_in,
                              void* d_out, int out_size) {
    const float* x         = (const float*)d_in[0];
    const float* edge_attr = (const float*)d_in[1];
    const float* node_W    = (const float*)d_in[2];
    const float* node_b    = (const float*)d_in[3];
    const float* edge_W    = (const float*)d_in[4];
    const float* edge_b    = (const float*)d_in[5];
    const float* attn_W    = (const float*)d_in[6];
    const float* attn_b    = (const float*)d_in[7];
    const float* eps       = (const float*)d_in[8];
    const float* W1        = (const float*)d_in[9];
    const float* b1        = (const float*)d_in[10];
    const float* bn1_g     = (const float*)d_in[11];
    const float* bn1_b     = (const float*)d_in[12];
    const float* W2        = (const float*)d_in[13];
    const float* b2        = (const float*)d_in[14];
    const float* bn_g      = (const float*)d_in[15];
    const float* bn_b      = (const float*)d_in[16];
    const int*   edge_index= (const int*)d_in[17];

    float *hA, *hB, *agg, *tbuf, *whi, *wlo; float2* pre;
    int *deg, *off, *cur, *esrc, *eidx;
    cudaGetSymbolAddress((void**)&hA,   g_h);
    cudaGetSymbolAddress((void**)&hB,   g_h2);
    cudaGetSymbolAddress((void**)&agg,  g_agg);
    cudaGetSymbolAddress((void**)&tbuf, g_t);
    cudaGetSymbolAddress((void**)&pre,  g_pre);
    cudaGetSymbolAddress((void**)&deg,  g_deg);
    cudaGetSymbolAddress((void**)&off,  g_off);
    cudaGetSymbolAddress((void**)&cur,  g_cur);
    cudaGetSymbolAddress((void**)&esrc, g_esrc);
    cudaGetSymbolAddress((void**)&eidx, g_eidx);
    cudaGetSymbolAddress((void**)&whi,  g_whi);
    cudaGetSymbolAddress((void**)&wlo,  g_wlo);

    const int* src_arr = edge_index;
    const int* dst_arr = edge_index + EE;
    const int mblk = (NN + 127) / 128;     // 313

    // Weight splits (offsets into whi/wlo)
    const int W1_OFF = 16384;
    const int W2_OFF = 16384 + 3 * 32768;  // 114688
    wsplit_kernel<<<(16384 + 255) / 256, 256>>>(node_W, whi, wlo, 16384);
    wsplit_kernel<<<(98304 + 255) / 256, 256>>>(W1, whi + W1_OFF, wlo + W1_OFF, 98304);
    wsplit_kernel<<<(98304 + 255) / 256, 256>>>(W2, whi + W2_OFF, wlo + W2_OFF, 98304);

    // CSR build
    zero_deg_kernel<<<(NN + 255) / 256, 256>>>(deg);
    count_kernel<<<(EE + 255) / 256, 256>>>(dst_arr, deg);
    scan_kernel<<<1, 1024>>>(deg, off, cur);
    fill_kernel<<<(EE + 255) / 256, 256>>>(src_arr, dst_arr, cur, esrc, eidx);

    // node encoder: h = x @ node_W + node_b
    tgemm_kernel<<<dim3(1, mblk), 256>>>(x, whi, wlo, node_b, nullptr, nullptr,
                                         hA, NN, DD, DD, 0, 0);

    const float* hcur = hA;
    float* hnext = hB;
    for (int l = 0; l < LL; l++) {
        prep_kernel<<<10000, 128>>>(hcur, attn_W + (size_t)l * 2 * DD, pre);
        edge_csr_kernel<<<444, 128>>>(hcur, edge_attr, off, esrc, eidx,
                                      edge_W + (size_t)l * EDD * DD,
                                      edge_b + (size_t)l * DD,
                                      pre, attn_b + l, eps + l, agg);
        // t = relu(bn1(agg @ W1 + b1))   [N,128]@[128,256]
        tgemm_kernel<<<dim3(2, mblk), 256>>>(agg,
                                             whi + W1_OFF + (size_t)l * 32768,
                                             wlo + W1_OFF + (size_t)l * 32768,
                                             b1 + (size_t)l * 2 * DD,
                                             bn1_g + (size_t)l * 2 * DD,
                                             bn1_b + (size_t)l * 2 * DD,
                                             tbuf, NN, DD, 2 * DD, 1, 1);
        // h' = [relu] bn(t @ W2 + b2)    [N,256]@[256,128]
        float* outp = (l == LL - 1) ? (float*)d_out : hnext;
        tgemm_kernel<<<dim3(1, mblk), 256>>>(tbuf,
                                             whi + W2_OFF + (size_t)l * 32768,
                                             wlo + W2_OFF + (size_t)l * 32768,
                                             b2 + (size_t)l * DD,
                                             bn_g + (size_t)l * DD,
                                             bn_b + (size_t)l * DD,
                                             outp, NN, 2 * DD, DD, (l < LL - 1) ? 1 : 0, 1);
        if (l < LL - 1) {
            hcur = outp;
            hnext = (outp == hA) ? hB : hA;
        }
    }
}

// round 15
// speedup vs baseline: 1.9875x; 1.0513x over previous
#include <cuda_runtime.h>
#include <cstdint>

// Problem constants
#define NN 40000
#define EE 640000
#define DD 128
#define EDD 16
#define LL 3
#define BN_INV 0.99999500003749978f  // 1/sqrt(1+1e-5)

// Scratch (no cudaMalloc allowed)
__device__ float  g_h[(size_t)NN * DD];
__device__ float  g_h2[(size_t)NN * DD];
__device__ float  g_agg[(size_t)NN * DD];
__device__ float  g_t[(size_t)NN * 2 * DD];
__device__ float2 g_pre[NN];
__device__ int    g_deg[NN];
__device__ int    g_off[NN + 1];
__device__ int    g_cur[NN];
__device__ int    g_esrc[EE];   // src node id per CSR slot
__device__ int    g_eidx[EE];   // original edge id per CSR slot
// tf32 hi/lo split of all GEMM weights:
//  [0, 16384)       node_W ; [16384, 114688) W1[3] ; [114688, 212992) W2[3]
#define WSPLIT_TOTAL 212992
__device__ float g_whi[WSPLIT_TOTAL];
__device__ float g_wlo[WSPLIT_TOTAL];

// ---- f32x2 helpers --------------------------------------------------------
__device__ __forceinline__ unsigned long long pack2(float lo, float hi) {
    unsigned long long r;
    asm("mov.b64 %0, {%1, %2};" : "=l"(r) : "f"(lo), "f"(hi));
    return r;
}
__device__ __forceinline__ void ffma2(unsigned long long& d,
                                      unsigned long long a,
                                      unsigned long long b) {
    asm("fma.rn.f32x2 %0, %1, %2, %0;" : "+l"(d) : "l"(a), "l"(b));
}
__device__ __forceinline__ void unpack2(unsigned long long v, float& lo, float& hi) {
    asm("mov.b64 {%0, %1}, %2;" : "=f"(lo), "=f"(hi) : "l"(v));
}
__device__ __forceinline__ float fold2(unsigned long long v) {
    float lo, hi; unpack2(v, lo, hi); return lo + hi;
}

// ---- tf32 helpers ---------------------------------------------------------
__device__ __forceinline__ void cvt_hilo(float raw, uint32_t& hi, uint32_t& lo) {
    asm("cvt.rna.tf32.f32 %0, %1;" : "=r"(hi) : "f"(raw));
    float rem = raw - __uint_as_float(hi);
    asm("cvt.rna.tf32.f32 %0, %1;" : "=r"(lo) : "f"(rem));
}
__device__ __forceinline__ void mma_tf32(float* d, const uint32_t* a,
                                         uint32_t b0, uint32_t b1) {
    asm volatile("mma.sync.aligned.m16n8k8.row.col.f32.tf32.tf32.f32 "
                 "{%0,%1,%2,%3}, {%4,%5,%6,%7}, {%8,%9}, {%0,%1,%2,%3};"
                 : "+f"(d[0]), "+f"(d[1]), "+f"(d[2]), "+f"(d[3])
                 : "r"(a[0]), "r"(a[1]), "r"(a[2]), "r"(a[3]),
                   "r"(b0), "r"(b1));
}

// ---------------------------------------------------------------------------
// weight split (all weights, one launch): hi = tf32(w), lo = tf32(w - hi)
// ---------------------------------------------------------------------------
__global__ void wsplit_all_kernel(const float* __restrict__ nW,
                                  const float* __restrict__ W1,
                                  const float* __restrict__ W2,
                                  float* __restrict__ whi,
                                  float* __restrict__ wlo) {
    int i = blockIdx.x * blockDim.x + threadIdx.x;
    if (i >= WSPLIT_TOTAL) return;
    float w;
    if (i < 16384)       w = nW[i];
    else if (i < 114688) w = W1[i - 16384];
    else                 w = W2[i - 114688];
    uint32_t hi, lo;
    cvt_hilo(w, hi, lo);
    whi[i] = __uint_as_float(hi);
    wlo[i] = __uint_as_float(lo);
}

// ---------------------------------------------------------------------------
// CSR build: (deg zeroed by cudaMemsetAsync) count -> scan -> fill
// ---------------------------------------------------------------------------
__global__ void count_kernel(const int* __restrict__ dst, int* __restrict__ deg) {
    int e = blockIdx.x * blockDim.x + threadIdx.x;
    if (e < EE) atomicAdd(&deg[dst[e]], 1);
}

__global__ __launch_bounds__(1024)
void scan_kernel(const int* __restrict__ deg, int* __restrict__ off,
                 int* __restrict__ cur) {
    __shared__ int part[1024];
    const int tid = threadIdx.x;
    const int per = (NN + 1023) / 1024;   // 40
    const int base = tid * per;
    int s = 0;
#pragma unroll 4
    for (int i = 0; i < per; i++) {
        const int n = base + i;
        if (n < NN) s += deg[n];
    }
    part[tid] = s;
    __syncthreads();
    for (int ofs = 1; ofs < 1024; ofs <<= 1) {
        int v = (tid >= ofs) ? part[tid - ofs] : 0;
        __syncthreads();
        part[tid] += v;
        __syncthreads();
    }
    int run = (tid > 0) ? part[tid - 1] : 0;   // exclusive prefix
    for (int i = 0; i < per; i++) {
        const int n = base + i;
        if (n < NN) {
            off[n] = run;
            cur[n] = run;
            run += deg[n];
        }
    }
    if (tid == 1023) off[NN] = EE;
}

__global__ void fill_kernel(const int* __restrict__ src,
                            const int* __restrict__ dst,
                            int* __restrict__ cur,
                            int* __restrict__ esrc,
                            int* __restrict__ eidx) {
    int e = blockIdx.x * blockDim.x + threadIdx.x;
    if (e >= EE) return;
    const int d = dst[e];
    const int p = atomicAdd(&cur[d], 1);
    esrc[p] = src[e];
    eidx[p] = e;
}

// ---------------------------------------------------------------------------
// prep: pre[n] = (h[n]·attn_W[0:128], h[n]·attn_W[128:256]). Warp per node.
// ---------------------------------------------------------------------------
__global__ __launch_bounds__(128)
void prep_kernel(const float* __restrict__ h,
                 const float* __restrict__ attn_W,   // [256]
                 float2* __restrict__ pre) {
    const int warp = (blockIdx.x * blockDim.x + threadIdx.x) >> 5;
    const int lane = threadIdx.x & 31;
    if (warp >= NN) return;
    const int d0 = lane * 4;
    const float4 hv = *(const float4*)(h + (size_t)warp * DD + d0);
    const float4 wi = *(const float4*)(attn_W + d0);
    const float4 wj = *(const float4*)(attn_W + DD + d0);
    float pi = hv.x * wi.x + hv.y * wi.y + hv.z * wi.z + hv.w * wi.w;
    float pj = hv.x * wj.x + hv.y * wj.y + hv.z * wj.z + hv.w * wj.w;
#pragma unroll
    for (int off = 16; off > 0; off >>= 1) {
        pi += __shfl_xor_sync(0xffffffffu, pi, off);
        pj += __shfl_xor_sync(0xffffffffu, pj, off);
    }
    if (lane == 0) pre[warp] = make_float2(pi, pj);
}

// ---------------------------------------------------------------------------
// per-edge accumulate helper (vmask multiplies AFTER relu; operands finite)
// ---------------------------------------------------------------------------
__device__ __forceinline__ void accum_edge(
    float4& acc, float a, float vmask, const float4 xj,
    const ulonglong2 qa, const ulonglong2 qb,
    const ulonglong2 qc, const ulonglong2 qd,
    const unsigned long long* __restrict__ wE2,
    const unsigned long long* __restrict__ ebp) {
    const unsigned long long ep[8] = {qa.x, qa.y, qb.x, qb.y,
                                      qc.x, qc.y, qd.x, qd.y};
    unsigned long long av0 = ebp[0], av1 = ebp[1], av2 = ebp[2], av3 = ebp[3];
#pragma unroll
    for (int k2 = 0; k2 < 8; k2++) {
        ffma2(av0, ep[k2], wE2[k2 * 4 + 0]);
        ffma2(av1, ep[k2], wE2[k2 * 4 + 1]);
        ffma2(av2, ep[k2], wE2[k2 * 4 + 2]);
        ffma2(av3, ep[k2], wE2[k2 * 4 + 3]);
    }
    acc.x = fmaf(fmaxf(fmaf(xj.x, a, fold2(av0)), 0.0f), vmask, acc.x);
    acc.y = fmaf(fmaxf(fmaf(xj.y, a, fold2(av1)), 0.0f), vmask, acc.y);
    acc.z = fmaf(fmaxf(fmaf(xj.z, a, fold2(av2)), 0.0f), vmask, acc.z);
    acc.w = fmaf(fmaxf(fmaf(xj.w, a, fold2(av3)), 0.0f), vmask, acc.w);
}

// ---------------------------------------------------------------------------
// CSR edge kernel v6: persistent warp-per-node + SOFTWARE PIPELINING.
// Iteration t+1's random loads (indices, h[src] gathers, pre.y) are issued
// BEFORE computing iteration t, hiding the idx->gather chain latency.
// ---------------------------------------------------------------------------
__global__ __launch_bounds__(128, 3)
void edge_csr_kernel(const float* __restrict__ h,
                     const float* __restrict__ edge_attr,
                     const int* __restrict__ off,
                     const int* __restrict__ esrc,
                     const int* __restrict__ eidx,
                     const float* __restrict__ edge_W,   // [16,128]
                     const float* __restrict__ edge_b,   // [128]
                     const float2* __restrict__ pre,     // [N]
                     const float* __restrict__ attn_b,   // [1]
                     const float* __restrict__ eps_l,
                     float* __restrict__ agg) {
    const int lane = threadIdx.x & 31;
    const int gwarp = (blockIdx.x * blockDim.x + threadIdx.x) >> 5;
    const int nwarp = (gridDim.x * blockDim.x) >> 5;
    const int d0 = lane * 4;

    unsigned long long wE2[32];
#pragma unroll
    for (int k2 = 0; k2 < 8; k2++) {
        const float4 wa = *(const float4*)(edge_W + (2 * k2) * DD + d0);
        const float4 wb = *(const float4*)(edge_W + (2 * k2 + 1) * DD + d0);
        wE2[k2 * 4 + 0] = pack2(wa.x, wb.x);
        wE2[k2 * 4 + 1] = pack2(wa.y, wb.y);
        wE2[k2 * 4 + 2] = pack2(wa.z, wb.z);
        wE2[k2 * 4 + 3] = pack2(wa.w, wb.w);
    }
    unsigned long long ebp[4];
    {
        const float4 eb = *(const float4*)(edge_b + d0);
        ebp[0] = pack2(eb.x, 0.0f); ebp[1] = pack2(eb.y, 0.0f);
        ebp[2] = pack2(eb.z, 0.0f); ebp[3] = pack2(eb.w, 0.0f);
    }
    const float ab = attn_b[0];
    const float s = 1.0f + eps_l[0];

#pragma unroll 1
    for (int node = gwarp; node < NN; node += nwarp) {
        const int beg = off[node], end = off[node + 1];
        const float pd = __ldg(&pre[node].x) + ab;

        float4 acc;
        {
            const float4 hv = *(const float4*)(h + (size_t)node * DD + d0);
            acc.x = hv.x * s; acc.y = hv.y * s; acc.z = hv.z * s; acc.w = hv.w * s;
        }

        if (beg < end) {
            // ---- stage 0 (prologue) ----
            const int jB0 = (beg + 1 < end) ? beg + 1 : beg;
            int   sA = esrc[beg],  iA = eidx[beg];
            int   sB = esrc[jB0],  iB = eidx[jB0];
            float mB = (beg + 1 < end) ? 1.0f : 0.0f;
            float4 xA = *(const float4*)(h + (size_t)sA * DD + d0);
            float4 xB = *(const float4*)(h + (size_t)sB * DD + d0);
            float  pA = __ldg(&pre[sA].y);
            float  pB = __ldg(&pre[sB].y);

            const int nIt = (end - beg + 1) >> 1;
#pragma unroll 1
            for (int it = 0; it < nIt; it++) {
                // ---- prefetch stage it+1 (clamped to beg when past end) ----
                const int nj  = beg + 2 * (it + 1);
                const int njA = (nj     < end) ? nj     : beg;
                const int njB = (nj + 1 < end) ? nj + 1 : beg;
                const float nmB = (nj + 1 < end) ? 1.0f : 0.0f;
                const int nsA = esrc[njA], niA = eidx[njA];
                const int nsB = esrc[njB], niB = eidx[njB];
                const float4 nxA = *(const float4*)(h + (size_t)nsA * DD + d0);
                const float4 nxB = *(const float4*)(h + (size_t)nsB * DD + d0);
                const float  npA = __ldg(&pre[nsA].y);
                const float  npB = __ldg(&pre[nsB].y);

                // ---- compute current stage (sequential ea loads here) ----
                const ulonglong2* eaA = (const ulonglong2*)(edge_attr + (size_t)iA * EDD);
                const ulonglong2* eaB = (const ulonglong2*)(edge_attr + (size_t)iB * EDD);
                const ulonglong2 qA0 = __ldg(eaA + 0), qA1 = __ldg(eaA + 1),
                                 qA2 = __ldg(eaA + 2), qA3 = __ldg(eaA + 3);
                const ulonglong2 qB0 = __ldg(eaB + 0), qB1 = __ldg(eaB + 1),
                                 qB2 = __ldg(eaB + 2), qB3 = __ldg(eaB + 3);
                const float aA = 1.0f / (1.0f + __expf(-(pd + pA)));
                const float aB = 1.0f / (1.0f + __expf(-(pd + pB)));
                accum_edge(acc, aA, 1.0f, xA, qA0, qA1, qA2, qA3, wE2, ebp);
                accum_edge(acc, aB, mB,   xB, qB0, qB1, qB2, qB3, wE2, ebp);

                // ---- rotate ----
                sA = nsA; iA = niA; sB = nsB; iB = niB;
                xA = nxA; xB = nxB; pA = npA; pB = npB; mB = nmB;
            }
        }

        *(float4*)(agg + (size_t)node * DD + d0) = acc;
    }
}

// ---------------------------------------------------------------------------
// 3xTF32 tensor-core GEMM (R14 verbatim): B pre-split hi/lo, 256 threads,
// 128x128 tile, warp tile 32x64, A ring 3 stages / B rings 4 stages.
// ---------------------------------------------------------------------------
__global__ __launch_bounds__(256, 2)
void tgemm_kernel(const float* __restrict__ A,
                  const float* __restrict__ Bhi, const float* __restrict__ Blo,
                  const float* __restrict__ bias,
                  const float* __restrict__ bn_g, const float* __restrict__ bn_b,
                  float* __restrict__ C,
                  int M, int K, int Nc, int do_relu, int do_bn) {
    __shared__ __align__(16) float As[3][8][136];
    __shared__ __align__(16) float Bh[4][8][136];
    __shared__ __align__(16) float Bl[4][8][136];

    const int tid = threadIdx.x;
    const int wid = tid >> 5;
    const int lane = tid & 31;
    const int gID = lane >> 2;
    const int tIG = lane & 3;
    const int warp_m = wid >> 1;
    const int warp_n = wid & 1;
    const int row0 = blockIdx.y * 128;
    const int col0 = blockIdx.x * 128;

    const int a_row = tid >> 1;
    const int a_col = (tid & 1) * 4;
    const int b_row = tid >> 5;
    const int b_col = lane * 4;

    const int gr = row0 + a_row;
    const bool av = gr < M;
    const float* aptr  = A   + (size_t)gr * K + a_col;
    const float* bhptr = Bhi + (size_t)b_row * Nc + col0 + b_col;
    const float* blptr = Blo + (size_t)b_row * Nc + col0 + b_col;

    const int nt = K >> 3;
    const float4 f40 = make_float4(0.f, 0.f, 0.f, 0.f);
    float4 ar;

#define LDG_A(k0) { ar = av ? *(const float4*)(aptr + (k0)) : f40; }
#define STS_A(stg) { As[stg][a_col+0][a_row] = ar.x; As[stg][a_col+1][a_row] = ar.y; \
                     As[stg][a_col+2][a_row] = ar.z; As[stg][a_col+3][a_row] = ar.w; }
#define CP_B(stg, k0) { \
    uint32_t _dh = (uint32_t)__cvta_generic_to_shared(&Bh[stg][b_row][b_col]); \
    uint32_t _dl = (uint32_t)__cvta_generic_to_shared(&Bl[stg][b_row][b_col]); \
    const float* _sh = bhptr + (size_t)(k0) * Nc; \
    const float* _sl = blptr + (size_t)(k0) * Nc; \
    asm volatile("cp.async.cg.shared.global [%0], [%1], 16;\n\t" \
                 "cp.async.cg.shared.global [%2], [%3], 16;\n\t" \
                 "cp.async.commit_group;\n" \
                 :: "r"(_dh), "l"(_sh), "r"(_dl), "l"(_sl) : "memory"); }

    float acc[2][8][4];
#pragma unroll
    for (int i = 0; i < 2; i++)
#pragma unroll
        for (int jj = 0; jj < 8; jj++)
#pragma unroll
            for (int c = 0; c < 4; c++) acc[i][jj][c] = 0.0f;

    LDG_A(0); CP_B(0, 0); STS_A(0);
    LDG_A(8); CP_B(1, 8);

#pragma unroll 1
    for (int t = 0; t < nt; t++) {
        const int sa = t % 3;
        const int sb = t & 3;
        if (t + 1 < nt) STS_A((t + 1) % 3);
        if (t + 2 < nt) { const int k0 = (t + 2) * 8; LDG_A(k0); CP_B((t + 2) & 3, k0); }
        const int rem = nt - 1 - t;
        if (rem >= 2)      asm volatile("cp.async.wait_group 2;" ::: "memory");
        else if (rem == 1) asm volatile("cp.async.wait_group 1;" ::: "memory");
        else               asm volatile("cp.async.wait_group 0;" ::: "memory");
        __syncthreads();

        uint32_t Ah[2][4], Al[2][4];
#pragma unroll
        for (int i = 0; i < 2; i++) {
            const int rb = warp_m * 32 + i * 16 + gID;
            const float r0 = As[sa][tIG    ][rb];
            const float r1 = As[sa][tIG    ][rb + 8];
            const float r2 = As[sa][tIG + 4][rb];
            const float r3 = As[sa][tIG + 4][rb + 8];
            cvt_hilo(r0, Ah[i][0], Al[i][0]);
            cvt_hilo(r1, Ah[i][1], Al[i][1]);
            cvt_hilo(r2, Ah[i][2], Al[i][2]);
            cvt_hilo(r3, Ah[i][3], Al[i][3]);
        }
#pragma unroll
        for (int jn = 0; jn < 8; jn++) {
            const int cb = warp_n * 64 + jn * 8 + gID;
            const uint32_t bh0 = __float_as_uint(Bh[sb][tIG    ][cb]);
            const uint32_t bh1 = __float_as_uint(Bh[sb][tIG + 4][cb]);
            const uint32_t bl0 = __float_as_uint(Bl[sb][tIG    ][cb]);
            const uint32_t bl1 = __float_as_uint(Bl[sb][tIG + 4][cb]);
#pragma unroll
            for (int i = 0; i < 2; i++) {
                mma_tf32(acc[i][jn], Ah[i], bh0, bh1);
                mma_tf32(acc[i][jn], Ah[i], bl0, bl1);
                mma_tf32(acc[i][jn], Al[i], bh0, bh1);
            }
        }
    }

#pragma unroll
    for (int i = 0; i < 2; i++) {
        const int r_lo = row0 + warp_m * 32 + i * 16 + gID;
        const int r_hi = r_lo + 8;
#pragma unroll
        for (int jn = 0; jn < 8; jn++) {
            const int c = col0 + warp_n * 64 + jn * 8 + tIG * 2;
            const float b0v = bias[c], b1v = bias[c + 1];
            float v00 = acc[i][jn][0] + b0v;
            float v01 = acc[i][jn][1] + b1v;
            float v10 = acc[i][jn][2] + b0v;
            float v11 = acc[i][jn][3] + b1v;
            if (do_bn) {
                const float g0 = bn_g[c] * BN_INV, g1 = bn_g[c + 1] * BN_INV;
                const float bb0 = bn_b[c], bb1 = bn_b[c + 1];
                v00 = fmaf(g0, v00, bb0); v01 = fmaf(g1, v01, bb1);
                v10 = fmaf(g0, v10, bb0); v11 = fmaf(g1, v11, bb1);
            }
            if (do_relu) {
                v00 = fmaxf(v00, 0.0f); v01 = fmaxf(v01, 0.0f);
                v10 = fmaxf(v10, 0.0f); v11 = fmaxf(v11, 0.0f);
            }
            if (r_lo < M) *(float2*)(C + (size_t)r_lo * Nc + c) = make_float2(v00, v01);
            if (r_hi < M) *(float2*)(C + (size_t)r_hi * Nc + c) = make_float2(v10, v11);
        }
    }
#undef LDG_A
#undef STS_A
#undef CP_B
}

// ---------------------------------------------------------------------------
extern "C" void kernel_launch(void* const* d_in, const int* in_sizes, int n_in,
                              void* d_out, int out_size) {
    const float* x         = (const float*)d_in[0];
    const float* edge_attr = (const float*)d_in[1];
    const float* node_W    = (const float*)d_in[2];
    const float* node_b    = (const float*)d_in[3];
    const float* edge_W    = (const float*)d_in[4];
    const float* edge_b    = (const float*)d_in[5];
    const float* attn_W    = (const float*)d_in[6];
    const float* attn_b    = (const float*)d_in[7];
    const float* eps       = (const float*)d_in[8];
    const float* W1        = (const float*)d_in[9];
    const float* b1        = (const float*)d_in[10];
    const float* bn1_g     = (const float*)d_in[11];
    const float* bn1_b     = (const float*)d_in[12];
    const float* W2        = (const float*)d_in[13];
    const float* b2        = (const float*)d_in[14];
    const float* bn_g      = (const float*)d_in[15];
    const float* bn_b      = (const float*)d_in[16];
    const int*   edge_index= (const int*)d_in[17];

    float *hA, *hB, *agg, *tbuf, *whi, *wlo; float2* pre;
    int *deg, *off, *cur, *esrc, *eidx;
    cudaGetSymbolAddress((void**)&hA,   g_h);
    cudaGetSymbolAddress((void**)&hB,   g_h2);
    cudaGetSymbolAddress((void**)&agg,  g_agg);
    cudaGetSymbolAddress((void**)&tbuf, g_t);
    cudaGetSymbolAddress((void**)&pre,  g_pre);
    cudaGetSymbolAddress((void**)&deg,  g_deg);
    cudaGetSymbolAddress((void**)&off,  g_off);
    cudaGetSymbolAddress((void**)&cur,  g_cur);
    cudaGetSymbolAddress((void**)&esrc, g_esrc);
    cudaGetSymbolAddress((void**)&eidx, g_eidx);
    cudaGetSymbolAddress((void**)&whi,  g_whi);
    cudaGetSymbolAddress((void**)&wlo,  g_wlo);

    const int* src_arr = edge_index;
    const int* dst_arr = edge_index + EE;
    const int mblk = (NN + 127) / 128;     // 313

    const int W1_OFF = 16384;
    const int W2_OFF = 114688;

    // Weight split (single launch)
    wsplit_all_kernel<<<(WSPLIT_TOTAL + 255) / 256, 256>>>(node_W, W1, W2, whi, wlo);

    // CSR build (deg zeroed via memset node — graph-capturable)
    cudaMemsetAsync(deg, 0, NN * sizeof(int));
    count_kernel<<<(EE + 255) / 256, 256>>>(dst_arr, deg);
    scan_kernel<<<1, 1024>>>(deg, off, cur);
    fill_kernel<<<(EE + 255) / 256, 256>>>(src_arr, dst_arr, cur, esrc, eidx);

    // node encoder: h = x @ node_W + node_b
    tgemm_kernel<<<dim3(1, mblk), 256>>>(x, whi, wlo, node_b, nullptr, nullptr,
                                         hA, NN, DD, DD, 0, 0);

    const float* hcur = hA;
    float* hnext = hB;
    for (int l = 0; l < LL; l++) {
        prep_kernel<<<10000, 128>>>(hcur, attn_W + (size_t)l * 2 * DD, pre);
        edge_csr_kernel<<<444, 128>>>(hcur, edge_attr, off, esrc, eidx,
                                      edge_W + (size_t)l * EDD * DD,
                                      edge_b + (size_t)l * DD,
                                      pre, attn_b + l, eps + l, agg);
        // t = relu(bn1(agg @ W1 + b1))   [N,128]@[128,256]
        tgemm_kernel<<<dim3(2, mblk), 256>>>(agg,
                                             whi + W1_OFF + (size_t)l * 32768,
                                             wlo + W1_OFF + (size_t)l * 32768,
                                             b1 + (size_t)l * 2 * DD,
                                             bn1_g + (size_t)l * 2 * DD,
                                             bn1_b + (size_t)l * 2 * DD,
                                             tbuf, NN, DD, 2 * DD, 1, 1);
        // h' = [relu] bn(t @ W2 + b2)    [N,256]@[256,128]
        float* outp = (l == LL - 1) ? (float*)d_out : hnext;
        tgemm_kernel<<<dim3(1, mblk), 256>>>(tbuf,
                                             whi + W2_OFF + (size_t)l * 32768,
                                             wlo + W2_OFF + (size_t)l * 32768,
                                             b2 + (size_t)l * DD,
                                             bn_g + (size_t)l * DD,
                                             bn_b + (size_t)l * DD,
                                             outp, NN, 2 * DD, DD, (l < LL - 1) ? 1 : 0, 1);
        if (l < LL - 1) {
            hcur = outp;
            hnext = (outp == hA) ? hB : hA;
        }
    }
}